// round 1
// baseline (speedup 1.0000x reference)
#include <cuda_runtime.h>
#include <cuda_bf16.h>
#include <math.h>

// Problem constants (fixed by the dataset)
#define S_LEN 2048
#define D_MODEL 1280
#define N_QKV 3840          // 3*D
#define N_HEADS 16
#define HEAD_DIM 80
#define MAX_SEG 256

// Scratch for the QKV projection result: [S, 3D] fp32 = 31.5 MB
__device__ float g_qkv[S_LEN * N_QKV];

// ---------------------------------------------------------------------------
// Kernel 1: QKV GEMM.  C[s,e] = sum_d A[s,d] * W[e,d] + bias[e]
// A: [2048,1280] row-major, W: [3840,1280] row-major (both K-contiguous).
// Tiles: BM=128, BN=64, BK=16. 256 threads, 8x4 micro-tile per thread.
// ---------------------------------------------------------------------------
#define BM 128
#define BN 64
#define BK 16

__global__ __launch_bounds__(256) void qkv_gemm_kernel(
    const float* __restrict__ A,
    const float* __restrict__ W,
    const float* __restrict__ bias,
    float* __restrict__ C)
{
    __shared__ float As[BK][BM + 4];
    __shared__ float Bs[BK][BN + 4];

    const int tid = threadIdx.x;
    const int bm = blockIdx.y * BM;
    const int bn = blockIdx.x * BN;

    const int tx = tid % 16;   // N direction, 4 cols each
    const int ty = tid / 16;   // M direction, 8 rows each

    float acc[8][4];
#pragma unroll
    for (int i = 0; i < 8; i++)
#pragma unroll
        for (int j = 0; j < 4; j++) acc[i][j] = 0.0f;

    // global-load indexing: each thread loads float4s
    const int lrow = tid / 4;          // 0..63
    const int lcol = (tid % 4) * 4;    // 0,4,8,12 within BK

    for (int k0 = 0; k0 < D_MODEL; k0 += BK) {
        // A tile: 128 rows x 16 cols -> 2 float4 per thread
#pragma unroll
        for (int i = 0; i < 2; i++) {
            int r = lrow + i * 64;
            float4 a = *(const float4*)&A[(size_t)(bm + r) * D_MODEL + k0 + lcol];
            As[lcol + 0][r] = a.x;
            As[lcol + 1][r] = a.y;
            As[lcol + 2][r] = a.z;
            As[lcol + 3][r] = a.w;
        }
        // B tile: 64 rows x 16 cols -> 1 float4 per thread
        {
            int r = lrow;
            float4 b = *(const float4*)&W[(size_t)(bn + r) * D_MODEL + k0 + lcol];
            Bs[lcol + 0][r] = b.x;
            Bs[lcol + 1][r] = b.y;
            Bs[lcol + 2][r] = b.z;
            Bs[lcol + 3][r] = b.w;
        }
        __syncthreads();

#pragma unroll
        for (int k = 0; k < BK; k++) {
            float ra[8], rb[4];
            float4 a0 = *(const float4*)&As[k][ty * 8 + 0];
            float4 a1 = *(const float4*)&As[k][ty * 8 + 4];
            ra[0] = a0.x; ra[1] = a0.y; ra[2] = a0.z; ra[3] = a0.w;
            ra[4] = a1.x; ra[5] = a1.y; ra[6] = a1.z; ra[7] = a1.w;
            float4 b0 = *(const float4*)&Bs[k][tx * 4];
            rb[0] = b0.x; rb[1] = b0.y; rb[2] = b0.z; rb[3] = b0.w;
#pragma unroll
            for (int i = 0; i < 8; i++)
#pragma unroll
                for (int j = 0; j < 4; j++)
                    acc[i][j] = fmaf(ra[i], rb[j], acc[i][j]);
        }
        __syncthreads();
    }

    // epilogue: add bias, store
#pragma unroll
    for (int i = 0; i < 8; i++) {
        int row = bm + ty * 8 + i;
        int col = bn + tx * 4;
        float4 o;
        o.x = acc[i][0] + bias[col + 0];
        o.y = acc[i][1] + bias[col + 1];
        o.z = acc[i][2] + bias[col + 2];
        o.w = acc[i][3] + bias[col + 3];
        *(float4*)&C[(size_t)row * N_QKV + col] = o;
    }
}

// ---------------------------------------------------------------------------
// Kernel 2: block-diagonal attention.
// grid = (nseg, H). Each CTA stages the segment's K,V for one head in smem
// (256x80 fp32 each = 160 KB), then each of 256 threads processes one query
// row with a 2-pass (stats, then output) softmax. Scores recomputed in pass 2.
// ---------------------------------------------------------------------------
__global__ __launch_bounds__(256, 1) void attn_kernel(
    const float* __restrict__ qkv,
    const int* __restrict__ cu_seqlens,
    float* __restrict__ out)
{
    extern __shared__ float smem[];
    float* Ks = smem;                       // [MAX_SEG][80]
    float* Vs = smem + MAX_SEG * HEAD_DIM;  // [MAX_SEG][80]

    const int seg = blockIdx.x;
    const int h = blockIdx.y;
    const int s0 = cu_seqlens[seg];
    int L = cu_seqlens[seg + 1] - s0;
    if (L > MAX_SEG) L = MAX_SEG;

    const int tid = threadIdx.x;

    // cooperative load of K,V for this (segment, head)
    for (int idx = tid; idx < L * HEAD_DIM; idx += 256) {
        int r = idx / HEAD_DIM;
        int d = idx - r * HEAD_DIM;
        size_t base = (size_t)(s0 + r) * N_QKV + h * HEAD_DIM + d;
        Ks[idx] = qkv[base + D_MODEL];       // K block
        Vs[idx] = qkv[base + 2 * D_MODEL];   // V block
    }
    __syncthreads();

    if (tid < L) {
        const float scale = 0.111803398874989485f;  // 1/sqrt(80)

        // load my query row into registers
        float q[HEAD_DIM];
        const float* qp = &qkv[(size_t)(s0 + tid) * N_QKV + h * HEAD_DIM];
#pragma unroll
        for (int d = 0; d < HEAD_DIM; d += 4) {
            float4 t = *(const float4*)&qp[d];
            q[d + 0] = t.x; q[d + 1] = t.y; q[d + 2] = t.z; q[d + 3] = t.w;
        }

        // pass 1: online softmax statistics
        float m = -INFINITY;
        float l = 0.0f;
        for (int j = 0; j < L; j++) {
            float s = 0.0f;
            const float* kp = &Ks[j * HEAD_DIM];
#pragma unroll
            for (int d = 0; d < HEAD_DIM; d += 4) {
                float4 kv = *(const float4*)&kp[d];
                s = fmaf(q[d + 0], kv.x, s);
                s = fmaf(q[d + 1], kv.y, s);
                s = fmaf(q[d + 2], kv.z, s);
                s = fmaf(q[d + 3], kv.w, s);
            }
            s *= scale;
            float mn = fmaxf(m, s);
            l = l * __expf(m - mn) + __expf(s - mn);
            m = mn;
        }
        const float inv_l = 1.0f / l;

        // pass 2: recompute scores, accumulate output
        float o[HEAD_DIM];
#pragma unroll
        for (int d = 0; d < HEAD_DIM; d++) o[d] = 0.0f;

        for (int j = 0; j < L; j++) {
            float s = 0.0f;
            const float* kp = &Ks[j * HEAD_DIM];
#pragma unroll
            for (int d = 0; d < HEAD_DIM; d += 4) {
                float4 kv = *(const float4*)&kp[d];
                s = fmaf(q[d + 0], kv.x, s);
                s = fmaf(q[d + 1], kv.y, s);
                s = fmaf(q[d + 2], kv.z, s);
                s = fmaf(q[d + 3], kv.w, s);
            }
            float p = __expf(s * scale - m) * inv_l;
            const float* vp = &Vs[j * HEAD_DIM];
#pragma unroll
            for (int d = 0; d < HEAD_DIM; d += 4) {
                float4 vv = *(const float4*)&vp[d];
                o[d + 0] = fmaf(p, vv.x, o[d + 0]);
                o[d + 1] = fmaf(p, vv.y, o[d + 1]);
                o[d + 2] = fmaf(p, vv.z, o[d + 2]);
                o[d + 3] = fmaf(p, vv.w, o[d + 3]);
            }
        }

        // write out: [b=0, s, h, hd] -> s*1280 + h*80 + d
        float* op = &out[(size_t)(s0 + tid) * (N_HEADS * HEAD_DIM) + h * HEAD_DIM];
#pragma unroll
        for (int d = 0; d < HEAD_DIM; d += 4) {
            float4 t;
            t.x = o[d + 0]; t.y = o[d + 1]; t.z = o[d + 2]; t.w = o[d + 3];
            *(float4*)&op[d] = t;
        }
    }
}

// ---------------------------------------------------------------------------
// Launcher
// ---------------------------------------------------------------------------
extern "C" void kernel_launch(void* const* d_in, const int* in_sizes, int n_in,
                              void* d_out, int out_size)
{
    const float* x    = (const float*)d_in[0];  // [2048,1,1280]
    const int*   cu   = (const int*)d_in[1];    // [9]
    const float* Wqkv = (const float*)d_in[2];  // [3840,1280]
    const float* bqkv = (const float*)d_in[3];  // [3840]
    float* out = (float*)d_out;                 // [1,2048,16,80]

    const int nseg = in_sizes[1] - 1;

    float* qkv;
    cudaGetSymbolAddress((void**)&qkv, g_qkv);

    // QKV projection
    dim3 g1(N_QKV / BN, S_LEN / BM);
    qkv_gemm_kernel<<<g1, 256>>>(x, Wqkv, bqkv, qkv);

    // block-diagonal attention
    const int smem_bytes = 2 * MAX_SEG * HEAD_DIM * sizeof(float);  // 160 KB
    cudaFuncSetAttribute(attn_kernel,
                         cudaFuncAttributeMaxDynamicSharedMemorySize, smem_bytes);
    dim3 g2(nseg, N_HEADS);
    attn_kernel<<<g2, 256, smem_bytes>>>(qkv, cu, out);
}

// round 3
// speedup vs baseline: 1.8329x; 1.8329x over previous
#include <cuda_runtime.h>
#include <cuda_bf16.h>
#include <math.h>
#include <cstdint>

// Problem constants
#define S_LEN 2048
#define D_MODEL 1280
#define N_QKV 3840
#define N_HEADS 16
#define HEAD_DIM 80
#define MAX_SEG 256

// Scratch for QKV projection result: [S, 3D] fp32
__device__ float g_qkv[S_LEN * N_QKV];

__device__ __forceinline__ uint32_t smem_u32(const void* p) {
    uint32_t a;
    asm("{ .reg .u64 t; cvta.to.shared.u64 t, %1; cvt.u32.u64 %0, t; }"
        : "=r"(a) : "l"(p));
    return a;
}

__device__ __forceinline__ void ldsm_x4(uint32_t* r, uint32_t addr) {
    asm volatile("ldmatrix.sync.aligned.m8n8.x4.shared.b16 {%0,%1,%2,%3}, [%4];"
                 : "=r"(r[0]), "=r"(r[1]), "=r"(r[2]), "=r"(r[3]) : "r"(addr));
}
__device__ __forceinline__ void ldsm_x2(uint32_t* r, uint32_t addr) {
    asm volatile("ldmatrix.sync.aligned.m8n8.x2.shared.b16 {%0,%1}, [%2];"
                 : "=r"(r[0]), "=r"(r[1]) : "r"(addr));
}
__device__ __forceinline__ void mma_bf16(float* c, const uint32_t* a, const uint32_t* b) {
    asm volatile(
        "mma.sync.aligned.m16n8k16.row.col.f32.bf16.bf16.f32 "
        "{%0,%1,%2,%3}, {%4,%5,%6,%7}, {%8,%9}, {%0,%1,%2,%3};"
        : "+f"(c[0]), "+f"(c[1]), "+f"(c[2]), "+f"(c[3])
        : "r"(a[0]), "r"(a[1]), "r"(a[2]), "r"(a[3]), "r"(b[0]), "r"(b[1]));
}

// ---------------------------------------------------------------------------
// Kernel 1: QKV GEMM, bf16 3-term error-split on mma.sync (HMMA).
// C[s,e] = sum_d A[s,d]*W[e,d] + bias[e]
// Tile: BM=128, BN=128, BK=32 fp32. 8 warps in 2(M)x4(N); warp tile 64x32.
// ---------------------------------------------------------------------------
#define GBM 128
#define GBN 128
#define GBK 32
#define NCHUNK (D_MODEL / GBK)   // 40
#define AST 40                    // smem row stride in bf16 (80 bytes, conflict-free)

__global__ __launch_bounds__(256) void qkv_gemm_mma(
    const float* __restrict__ A,
    const float* __restrict__ W,
    const float* __restrict__ bias,
    float* __restrict__ C)
{
    __shared__ __align__(16) __nv_bfloat16 As_hi[GBM * AST];
    __shared__ __align__(16) __nv_bfloat16 As_lo[GBM * AST];
    __shared__ __align__(16) __nv_bfloat16 Bs_hi[GBN * AST];
    __shared__ __align__(16) __nv_bfloat16 Bs_lo[GBN * AST];

    const int tid = threadIdx.x;
    const int wid = tid >> 5;
    const int lane = tid & 31;
    const int wm = wid >> 2;        // 0..1
    const int wn = wid & 3;         // 0..3
    const int bn = blockIdx.x * GBN;
    const int bm = blockIdx.y * GBM;

    float acc[4][4][4];
#pragma unroll
    for (int i = 0; i < 4; i++)
#pragma unroll
        for (int j = 0; j < 4; j++)
#pragma unroll
            for (int k = 0; k < 4; k++) acc[i][j][k] = 0.0f;

    // global-load indexing: 128 rows x 8 float4 per tile; thread covers 4 each
    const int grow = tid >> 3;          // 0..31 step: idx>>3
    // per i: idx = i*256+tid -> row = idx>>3 = i*32 + (tid>>3), c4 = tid&7
    const int gc4 = tid & 7;

    float4 aregs[4], bregs[4];
#pragma unroll
    for (int i = 0; i < 4; i++) {
        int row = i * 32 + grow;
        aregs[i] = *(const float4*)&A[(size_t)(bm + row) * D_MODEL + gc4 * 4];
        bregs[i] = *(const float4*)&W[(size_t)(bn + row) * D_MODEL + gc4 * 4];
    }

    // precompute ldmatrix lane addressing
    const int lr = lane & 7;
    const int lsub = lane >> 3;                    // 0..3
    const int a_row_off = (lsub & 1) * 8 + lr;     // within m16 block
    const int a_k_off = (lsub >> 1) * 8;           // 0 or 8
    const int b_k_off = (lsub & 1) * 8;

    const uint32_t sAhi = smem_u32(As_hi), sAlo = smem_u32(As_lo);
    const uint32_t sBhi = smem_u32(Bs_hi), sBlo = smem_u32(Bs_lo);

    for (int c = 0; c < NCHUNK; c++) {
        // split fp32 -> bf16 hi/lo and store to smem
#pragma unroll
        for (int i = 0; i < 4; i++) {
            int row = i * 32 + grow;
            int doff = row * AST + gc4 * 4;   // bf16 units
            float4 v = aregs[i];
            __nv_bfloat16 hx = __float2bfloat16(v.x), hy = __float2bfloat16(v.y);
            __nv_bfloat16 hz = __float2bfloat16(v.z), hw = __float2bfloat16(v.w);
            __nv_bfloat162 h01 = __halves2bfloat162(hx, hy);
            __nv_bfloat162 h23 = __halves2bfloat162(hz, hw);
            uint2 hu; hu.x = *(uint32_t*)&h01; hu.y = *(uint32_t*)&h23;
            *(uint2*)&As_hi[doff] = hu;
            __nv_bfloat162 l01 = __halves2bfloat162(
                __float2bfloat16(v.x - __bfloat162float(hx)),
                __float2bfloat16(v.y - __bfloat162float(hy)));
            __nv_bfloat162 l23 = __halves2bfloat162(
                __float2bfloat16(v.z - __bfloat162float(hz)),
                __float2bfloat16(v.w - __bfloat162float(hw)));
            uint2 lu; lu.x = *(uint32_t*)&l01; lu.y = *(uint32_t*)&l23;
            *(uint2*)&As_lo[doff] = lu;

            v = bregs[i];
            hx = __float2bfloat16(v.x); hy = __float2bfloat16(v.y);
            hz = __float2bfloat16(v.z); hw = __float2bfloat16(v.w);
            h01 = __halves2bfloat162(hx, hy);
            h23 = __halves2bfloat162(hz, hw);
            hu.x = *(uint32_t*)&h01; hu.y = *(uint32_t*)&h23;
            *(uint2*)&Bs_hi[doff] = hu;
            l01 = __halves2bfloat162(
                __float2bfloat16(v.x - __bfloat162float(hx)),
                __float2bfloat16(v.y - __bfloat162float(hy)));
            l23 = __halves2bfloat162(
                __float2bfloat16(v.z - __bfloat162float(hz)),
                __float2bfloat16(v.w - __bfloat162float(hw)));
            lu.x = *(uint32_t*)&l01; lu.y = *(uint32_t*)&l23;
            *(uint2*)&Bs_lo[doff] = lu;
        }
        __syncthreads();

        // prefetch next chunk
        if (c + 1 < NCHUNK) {
            int k0 = (c + 1) * GBK;
#pragma unroll
            for (int i = 0; i < 4; i++) {
                int row = i * 32 + grow;
                aregs[i] = *(const float4*)&A[(size_t)(bm + row) * D_MODEL + k0 + gc4 * 4];
                bregs[i] = *(const float4*)&W[(size_t)(bn + row) * D_MODEL + k0 + gc4 * 4];
            }
        }

        // compute: 2 k16 steps
#pragma unroll
        for (int ks = 0; ks < 2; ks++) {
            uint32_t ah[4][4], al[4][4], bh[4][2], bl[4][2];
#pragma unroll
            for (int mb = 0; mb < 4; mb++) {
                uint32_t off = (uint32_t)((wm * 64 + mb * 16 + a_row_off) * AST
                                          + ks * 16 + a_k_off) * 2;
                ldsm_x4(ah[mb], sAhi + off);
                ldsm_x4(al[mb], sAlo + off);
            }
#pragma unroll
            for (int nb = 0; nb < 4; nb++) {
                uint32_t off = (uint32_t)((wn * 32 + nb * 8 + lr) * AST
                                          + ks * 16 + b_k_off) * 2;
                ldsm_x2(bh[nb], sBhi + off);
                ldsm_x2(bl[nb], sBlo + off);
            }
#pragma unroll
            for (int mb = 0; mb < 4; mb++)
#pragma unroll
                for (int nb = 0; nb < 4; nb++) {
                    mma_bf16(acc[mb][nb], ah[mb], bh[nb]);
                    mma_bf16(acc[mb][nb], ah[mb], bl[nb]);
                    mma_bf16(acc[mb][nb], al[mb], bh[nb]);
                }
        }
        __syncthreads();
    }

    // epilogue: acc layout per thread: c0=(g,2c), c1=(g,2c+1), c2=(g+8,2c), c3=(g+8,2c+1)
    const int g = lane >> 2;
    const int cc = lane & 3;
#pragma unroll
    for (int mb = 0; mb < 4; mb++) {
#pragma unroll
        for (int nb = 0; nb < 4; nb++) {
            int row = bm + wm * 64 + mb * 16 + g;
            int col = bn + wn * 32 + nb * 8 + cc * 2;
            float2 bv = *(const float2*)&bias[col];
            float2 o0, o1;
            o0.x = acc[mb][nb][0] + bv.x;
            o0.y = acc[mb][nb][1] + bv.y;
            o1.x = acc[mb][nb][2] + bv.x;
            o1.y = acc[mb][nb][3] + bv.y;
            *(float2*)&C[(size_t)row * N_QKV + col] = o0;
            *(float2*)&C[(size_t)(row + 8) * N_QKV + col] = o1;
        }
    }
}

// ---------------------------------------------------------------------------
// Kernel 2: block-diagonal attention, single-pass online softmax.
// ---------------------------------------------------------------------------
__global__ __launch_bounds__(256, 1) void attn_kernel(
    const float* __restrict__ qkv,
    const int* __restrict__ cu_seqlens,
    float* __restrict__ out)
{
    extern __shared__ float smemf[];
    float* Ks = smemf;
    float* Vs = smemf + MAX_SEG * HEAD_DIM;

    const int seg = blockIdx.x;
    const int h = blockIdx.y;
    const int s0 = cu_seqlens[seg];
    int L = cu_seqlens[seg + 1] - s0;
    if (L > MAX_SEG) L = MAX_SEG;

    const int tid = threadIdx.x;

    for (int idx = tid; idx < L * HEAD_DIM; idx += 256) {
        int r = idx / HEAD_DIM;
        int d = idx - r * HEAD_DIM;
        size_t base = (size_t)(s0 + r) * N_QKV + h * HEAD_DIM + d;
        Ks[idx] = qkv[base + D_MODEL];
        Vs[idx] = qkv[base + 2 * D_MODEL];
    }
    __syncthreads();

    if (tid < L) {
        const float scale = 0.111803398874989485f;  // 1/sqrt(80)

        float q[HEAD_DIM];
        const float* qp = &qkv[(size_t)(s0 + tid) * N_QKV + h * HEAD_DIM];
#pragma unroll
        for (int d = 0; d < HEAD_DIM; d += 4) {
            float4 t = *(const float4*)&qp[d];
            q[d + 0] = t.x * scale; q[d + 1] = t.y * scale;
            q[d + 2] = t.z * scale; q[d + 3] = t.w * scale;
        }

        float m = -INFINITY;
        float l = 0.0f;
        float o[HEAD_DIM];
#pragma unroll
        for (int d = 0; d < HEAD_DIM; d++) o[d] = 0.0f;

        for (int j = 0; j < L; j++) {
            float s0a = 0.f, s1a = 0.f, s2a = 0.f, s3a = 0.f;
            const float4* kp = (const float4*)&Ks[j * HEAD_DIM];
#pragma unroll
            for (int d4 = 0; d4 < HEAD_DIM / 4; d4++) {
                float4 kv = kp[d4];
                s0a = fmaf(q[d4 * 4 + 0], kv.x, s0a);
                s1a = fmaf(q[d4 * 4 + 1], kv.y, s1a);
                s2a = fmaf(q[d4 * 4 + 2], kv.z, s2a);
                s3a = fmaf(q[d4 * 4 + 3], kv.w, s3a);
            }
            float s = (s0a + s1a) + (s2a + s3a);

            if (s > m) {
                float corr = __expf(m - s);
                l *= corr;
#pragma unroll
                for (int d = 0; d < HEAD_DIM; d++) o[d] *= corr;
                m = s;
            }
            float p = __expf(s - m);
            l += p;
            const float4* vp = (const float4*)&Vs[j * HEAD_DIM];
#pragma unroll
            for (int d4 = 0; d4 < HEAD_DIM / 4; d4++) {
                float4 vv = vp[d4];
                o[d4 * 4 + 0] = fmaf(p, vv.x, o[d4 * 4 + 0]);
                o[d4 * 4 + 1] = fmaf(p, vv.y, o[d4 * 4 + 1]);
                o[d4 * 4 + 2] = fmaf(p, vv.z, o[d4 * 4 + 2]);
                o[d4 * 4 + 3] = fmaf(p, vv.w, o[d4 * 4 + 3]);
            }
        }
        const float inv_l = 1.0f / l;

        float* op = &out[(size_t)(s0 + tid) * (N_HEADS * HEAD_DIM) + h * HEAD_DIM];
#pragma unroll
        for (int d = 0; d < HEAD_DIM; d += 4) {
            float4 t;
            t.x = o[d + 0] * inv_l; t.y = o[d + 1] * inv_l;
            t.z = o[d + 2] * inv_l; t.w = o[d + 3] * inv_l;
            *(float4*)&op[d] = t;
        }
    }
}

// ---------------------------------------------------------------------------
// Launcher
// ---------------------------------------------------------------------------
extern "C" void kernel_launch(void* const* d_in, const int* in_sizes, int n_in,
                              void* d_out, int out_size)
{
    const float* x    = (const float*)d_in[0];
    const int*   cu   = (const int*)d_in[1];
    const float* Wqkv = (const float*)d_in[2];
    const float* bqkv = (const float*)d_in[3];
    float* out = (float*)d_out;

    const int nseg = in_sizes[1] - 1;

    float* qkv;
    cudaGetSymbolAddress((void**)&qkv, g_qkv);

    dim3 g1(N_QKV / GBN, S_LEN / GBM);   // 30 x 16
    qkv_gemm_mma<<<g1, 256>>>(x, Wqkv, bqkv, qkv);

    const int smem_bytes = 2 * MAX_SEG * HEAD_DIM * sizeof(float);
    cudaFuncSetAttribute(attn_kernel,
                         cudaFuncAttributeMaxDynamicSharedMemorySize, smem_bytes);
    dim3 g2(nseg, N_HEADS);
    attn_kernel<<<g2, 256, smem_bytes>>>(qkv, cu, out);
}

// round 4
// speedup vs baseline: 2.5654x; 1.3996x over previous
#include <cuda_runtime.h>
#include <cuda_bf16.h>
#include <math.h>
#include <cstdint>

// Problem constants (fixed by the dataset)
#define S_LEN 2048
#define D_MODEL 1280
#define N_QKV 3840
#define N_HEADS 16
#define HEAD_DIM 80
#define SEG_LEN 256

// Global scratch
__device__ float g_qkv[S_LEN * N_QKV];
__device__ __nv_bfloat16 g_xh[S_LEN * D_MODEL];
__device__ __nv_bfloat16 g_xl[S_LEN * D_MODEL];
__device__ __nv_bfloat16 g_wh[N_QKV * D_MODEL];
__device__ __nv_bfloat16 g_wl[N_QKV * D_MODEL];

// ---------------------------------------------------------------------------
// Helpers
// ---------------------------------------------------------------------------
__device__ __forceinline__ uint32_t smem_u32(const void* p) {
    uint32_t a;
    asm("{ .reg .u64 t; cvta.to.shared.u64 t, %1; cvt.u32.u64 %0, t; }"
        : "=r"(a) : "l"(p));
    return a;
}
__device__ __forceinline__ void ldsm_x4(uint32_t* r, uint32_t addr) {
    asm volatile("ldmatrix.sync.aligned.m8n8.x4.shared.b16 {%0,%1,%2,%3}, [%4];"
                 : "=r"(r[0]), "=r"(r[1]), "=r"(r[2]), "=r"(r[3]) : "r"(addr));
}
__device__ __forceinline__ void ldsm_x2(uint32_t* r, uint32_t addr) {
    asm volatile("ldmatrix.sync.aligned.m8n8.x2.shared.b16 {%0,%1}, [%2];"
                 : "=r"(r[0]), "=r"(r[1]) : "r"(addr));
}
__device__ __forceinline__ void mma_bf16(float* c, const uint32_t* a, const uint32_t* b) {
    asm volatile(
        "mma.sync.aligned.m16n8k16.row.col.f32.bf16.bf16.f32 "
        "{%0,%1,%2,%3}, {%4,%5,%6,%7}, {%8,%9}, {%0,%1,%2,%3};"
        : "+f"(c[0]), "+f"(c[1]), "+f"(c[2]), "+f"(c[3])
        : "r"(a[0]), "r"(a[1]), "r"(a[2]), "r"(a[3]), "r"(b[0]), "r"(b[1]));
}
__device__ __forceinline__ void cp16(uint32_t dst, const void* src) {
    asm volatile("cp.async.ca.shared.global [%0], [%1], 16;"
                 :: "r"(dst), "l"(src));
}
#define CP_COMMIT() asm volatile("cp.async.commit_group;" ::: "memory")
#define CP_WAIT1() asm volatile("cp.async.wait_group 1;" ::: "memory")
#define CP_WAIT0() asm volatile("cp.async.wait_group 0;" ::: "memory")

__device__ __forceinline__ void split2(float v, __nv_bfloat16& h, __nv_bfloat16& l) {
    h = __float2bfloat16(v);
    l = __float2bfloat16(v - __bfloat162float(h));
}
// pack (a,b) -> bf16x2 reg, a in low half (element k), b in high (element k+1)
__device__ __forceinline__ void split_pack2(float a, float b, uint32_t& hi, uint32_t& lo) {
    __nv_bfloat16 ha = __float2bfloat16(a), hb = __float2bfloat16(b);
    __nv_bfloat162 H = __halves2bfloat162(ha, hb);
    hi = *(uint32_t*)&H;
    __nv_bfloat16 la = __float2bfloat16(a - __bfloat162float(ha));
    __nv_bfloat16 lb = __float2bfloat16(b - __bfloat162float(hb));
    __nv_bfloat162 L2 = __halves2bfloat162(la, lb);
    lo = *(uint32_t*)&L2;
}

// ---------------------------------------------------------------------------
// Kernel 0: split x and W into bf16 hi/lo global arrays
// ---------------------------------------------------------------------------
#define NX4 (S_LEN * D_MODEL / 4)   // 655360
#define NW4 (N_QKV * D_MODEL / 4)   // 1228800

__global__ __launch_bounds__(256) void split_kernel(
    const float* __restrict__ x, const float* __restrict__ w)
{
    int i = blockIdx.x * blockDim.x + threadIdx.x;
    if (i >= NX4 + NW4) return;
    const float4* src;
    uint2 *dh, *dl;
    int off;
    if (i < NX4) { src = (const float4*)x; dh = (uint2*)g_xh; dl = (uint2*)g_xl; off = i; }
    else { src = (const float4*)w; dh = (uint2*)g_wh; dl = (uint2*)g_wl; off = i - NX4; }
    float4 v = src[off];
    __nv_bfloat16 hx, hy, hz, hw, lx, ly, lz, lw;
    split2(v.x, hx, lx); split2(v.y, hy, ly);
    split2(v.z, hz, lz); split2(v.w, hw, lw);
    __nv_bfloat162 a = __halves2bfloat162(hx, hy), b = __halves2bfloat162(hz, hw);
    uint2 H; H.x = *(uint32_t*)&a; H.y = *(uint32_t*)&b;
    dh[off] = H;
    a = __halves2bfloat162(lx, ly); b = __halves2bfloat162(lz, lw);
    uint2 L; L.x = *(uint32_t*)&a; L.y = *(uint32_t*)&b;
    dl[off] = L;
}

// ---------------------------------------------------------------------------
// Kernel 1: QKV GEMM, bf16 3-split HMMA, cp.async double-buffered.
// ---------------------------------------------------------------------------
#define GBM 128
#define GBN 128
#define GBK 32
#define NCHUNK (D_MODEL / GBK)   // 40
#define AST 40                   // smem row stride in bf16 (80 B)
#define ARR_BYTES (128 * AST * 2)        // 10240
#define STAGE_BYTES (4 * ARR_BYTES)      // 40960

__global__ __launch_bounds__(256) void qkv_gemm_mma(
    const float* __restrict__ bias,
    float* __restrict__ C)
{
    extern __shared__ char smem[];
    const uint32_t sb = smem_u32(smem);

    const int tid = threadIdx.x;
    const int wid = tid >> 5;
    const int lane = tid & 31;
    const int wm = wid >> 2;
    const int wn = wid & 3;
    const int bn = blockIdx.x * GBN;
    const int bm = blockIdx.y * GBM;

    float acc[4][4][4];
#pragma unroll
    for (int i = 0; i < 4; i++)
#pragma unroll
        for (int j = 0; j < 4; j++)
#pragma unroll
            for (int k = 0; k < 4; k++) acc[i][j][k] = 0.0f;

    const int lrow = tid >> 2;   // 0..63
    const int lch = tid & 3;     // 16B chunk within 64B row

    const int lr = lane & 7;
    const int lsub = lane >> 3;
    const int a_row_off = (lsub & 1) * 8 + lr;
    const int a_k_off = (lsub >> 1) * 8;
    const int b_k_off = (lsub & 1) * 8;

    // stage loader
    auto load_stage = [&](int c, int st) {
        uint32_t dbase = sb + st * STAGE_BYTES;
        size_t soff = (size_t)c * GBK + lch * 8;
#pragma unroll
        for (int i = 0; i < 2; i++) {
            int r = lrow + i * 64;
            uint32_t d = dbase + (uint32_t)(r * AST + lch * 8) * 2;
            cp16(d + 0 * ARR_BYTES, g_xh + (size_t)(bm + r) * D_MODEL + soff);
            cp16(d + 1 * ARR_BYTES, g_xl + (size_t)(bm + r) * D_MODEL + soff);
            cp16(d + 2 * ARR_BYTES, g_wh + (size_t)(bn + r) * D_MODEL + soff);
            cp16(d + 3 * ARR_BYTES, g_wl + (size_t)(bn + r) * D_MODEL + soff);
        }
        CP_COMMIT();
    };

    load_stage(0, 0);

    for (int c = 0; c < NCHUNK; c++) {
        const int cur = c & 1;
        if (c + 1 < NCHUNK) {
            load_stage(c + 1, cur ^ 1);
            CP_WAIT1();
        } else {
            CP_WAIT0();
        }
        __syncthreads();

        const uint32_t sAh = sb + cur * STAGE_BYTES;
        const uint32_t sAl = sAh + ARR_BYTES;
        const uint32_t sBh = sAh + 2 * ARR_BYTES;
        const uint32_t sBl = sAh + 3 * ARR_BYTES;

#pragma unroll
        for (int ks = 0; ks < 2; ks++) {
            uint32_t ah[4][4], al[4][4], bh[4][2], bl[4][2];
#pragma unroll
            for (int mb = 0; mb < 4; mb++) {
                uint32_t off = (uint32_t)((wm * 64 + mb * 16 + a_row_off) * AST
                                          + ks * 16 + a_k_off) * 2;
                ldsm_x4(ah[mb], sAh + off);
                ldsm_x4(al[mb], sAl + off);
            }
#pragma unroll
            for (int nb = 0; nb < 4; nb++) {
                uint32_t off = (uint32_t)((wn * 32 + nb * 8 + lr) * AST
                                          + ks * 16 + b_k_off) * 2;
                ldsm_x2(bh[nb], sBh + off);
                ldsm_x2(bl[nb], sBl + off);
            }
#pragma unroll
            for (int mb = 0; mb < 4; mb++)
#pragma unroll
                for (int nb = 0; nb < 4; nb++) {
                    mma_bf16(acc[mb][nb], ah[mb], bh[nb]);
                    mma_bf16(acc[mb][nb], ah[mb], bl[nb]);
                    mma_bf16(acc[mb][nb], al[mb], bh[nb]);
                }
        }
        __syncthreads();
    }

    const int g = lane >> 2;
    const int cc = lane & 3;
#pragma unroll
    for (int mb = 0; mb < 4; mb++) {
#pragma unroll
        for (int nb = 0; nb < 4; nb++) {
            int row = bm + wm * 64 + mb * 16 + g;
            int col = bn + wn * 32 + nb * 8 + cc * 2;
            float2 bv = *(const float2*)&bias[col];
            float2 o0, o1;
            o0.x = acc[mb][nb][0] + bv.x;
            o0.y = acc[mb][nb][1] + bv.y;
            o1.x = acc[mb][nb][2] + bv.x;
            o1.y = acc[mb][nb][3] + bv.y;
            *(float2*)&C[(size_t)row * N_QKV + col] = o0;
            *(float2*)&C[(size_t)(row + 8) * N_QKV + col] = o1;
        }
    }
}

// ---------------------------------------------------------------------------
// Kernel 2: block-diagonal flash attention on HMMA, bf16 3-split.
// One CTA per (segment, head). 8 warps; warp owns 16 q-rows of a 128-row
// Q tile; 2 Q tiles per CTA. K and V^T staged hi/lo in smem.
// ---------------------------------------------------------------------------
#define AK 88    // Q/K row stride (bf16): 176 B, conflict-free for ldmatrix
#define AV 264   // V^T row stride (bf16): 528 B, conflict-free

#define OFF_QH 0
#define OFF_QL (OFF_QH + 128 * AK * 2)   // 22528
#define OFF_KH (OFF_QL + 128 * AK * 2)   // 45056
#define OFF_KL (OFF_KH + 256 * AK * 2)   // 90112
#define OFF_VH (OFF_KL + 256 * AK * 2)   // 135168
#define OFF_VL (OFF_VH + 80 * AV * 2)    // 177408
#define ATTN_SMEM (OFF_VL + 80 * AV * 2) // 219648

__global__ __launch_bounds__(256, 1) void attn_mma(
    const float* __restrict__ qkv,
    const int* __restrict__ cu_seqlens,
    float* __restrict__ out)
{
    extern __shared__ char smem[];
    const uint32_t sb = smem_u32(smem);
    __nv_bfloat16* Qh = (__nv_bfloat16*)(smem + OFF_QH);
    __nv_bfloat16* Ql = (__nv_bfloat16*)(smem + OFF_QL);
    __nv_bfloat16* Kh = (__nv_bfloat16*)(smem + OFF_KH);
    __nv_bfloat16* Kl = (__nv_bfloat16*)(smem + OFF_KL);
    __nv_bfloat16* Vh = (__nv_bfloat16*)(smem + OFF_VH);
    __nv_bfloat16* Vl = (__nv_bfloat16*)(smem + OFF_VL);

    const int seg = blockIdx.x;
    const int h = blockIdx.y;
    const int s0 = cu_seqlens[seg];

    const int tid = threadIdx.x;
    const int wid = tid >> 5;
    const int lane = tid & 31;
    const int lr = lane & 7;
    const int lsub = lane >> 3;
    const int a_row_off = (lsub & 1) * 8 + lr;
    const int a_k_off = (lsub >> 1) * 8;
    const int b_k_off = (lsub & 1) * 8;
    const int g = lane >> 2;
    const int qc = lane & 3;
    const int mr = wid * 16;

    const float scale = 0.111803398874989485f;  // 1/sqrt(80)

    // ---- load K (hi/lo) and V^T (hi/lo) ----
    for (int i = tid; i < SEG_LEN * HEAD_DIM; i += 256) {
        int kv = i / HEAD_DIM;
        int d = i - kv * HEAD_DIM;
        size_t base = (size_t)(s0 + kv) * N_QKV + h * HEAD_DIM + d;
        __nv_bfloat16 hh, ll;
        split2(qkv[base + D_MODEL], hh, ll);
        Kh[kv * AK + d] = hh;
        Kl[kv * AK + d] = ll;
        split2(qkv[base + 2 * D_MODEL], hh, ll);
        Vh[d * AV + kv] = hh;
        Vl[d * AV + kv] = ll;
    }
    // ---- load Q tile 0 (scaled, hi/lo) ----
    for (int i = tid; i < 128 * HEAD_DIM; i += 256) {
        int r = i / HEAD_DIM;
        int d = i - r * HEAD_DIM;
        float v = qkv[(size_t)(s0 + r) * N_QKV + h * HEAD_DIM + d] * scale;
        __nv_bfloat16 hh, ll;
        split2(v, hh, ll);
        Qh[r * AK + d] = hh;
        Ql[r * AK + d] = ll;
    }
    __syncthreads();

    const uint32_t qh_base = sb + OFF_QH + (uint32_t)((mr + a_row_off) * AK + a_k_off) * 2;
    const uint32_t ql_base = sb + OFF_QL + (uint32_t)((mr + a_row_off) * AK + a_k_off) * 2;
    const uint32_t kh_base = sb + OFF_KH + (uint32_t)(lr * AK + b_k_off) * 2;
    const uint32_t kl_base = sb + OFF_KL + (uint32_t)(lr * AK + b_k_off) * 2;
    const uint32_t vh_base = sb + OFF_VH + (uint32_t)(lr * AV + b_k_off) * 2;
    const uint32_t vl_base = sb + OFF_VL + (uint32_t)(lr * AV + b_k_off) * 2;

    for (int qt = 0; qt < 2; qt++) {
        if (qt) {
            __syncthreads();
            for (int i = tid; i < 128 * HEAD_DIM; i += 256) {
                int r = i / HEAD_DIM;
                int d = i - r * HEAD_DIM;
                float v = qkv[(size_t)(s0 + 128 + r) * N_QKV + h * HEAD_DIM + d] * scale;
                __nv_bfloat16 hh, ll;
                split2(v, hh, ll);
                Qh[r * AK + d] = hh;
                Ql[r * AK + d] = ll;
            }
            __syncthreads();
        }

        float oacc[10][4];
#pragma unroll
        for (int vb = 0; vb < 10; vb++)
#pragma unroll
            for (int k = 0; k < 4; k++) oacc[vb][k] = 0.0f;
        float m0 = -1e30f, m1 = -1e30f, l0 = 0.0f, l1 = 0.0f;

        for (int kt = 0; kt < 4; kt++) {
            // ---- S = Q K^T on this 64-wide KV tile ----
            float sacc[8][4];
#pragma unroll
            for (int nb = 0; nb < 8; nb++)
#pragma unroll
                for (int k = 0; k < 4; k++) sacc[nb][k] = 0.0f;

#pragma unroll
            for (int kb = 0; kb < 5; kb++) {
                uint32_t ah[4], al[4];
                ldsm_x4(ah, qh_base + kb * 32);
                ldsm_x4(al, ql_base + kb * 32);
#pragma unroll
                for (int nb = 0; nb < 8; nb++) {
                    uint32_t bh[2], bl[2];
                    uint32_t ko = (uint32_t)((kt * 64 + nb * 8) * AK + kb * 16) * 2;
                    ldsm_x2(bh, kh_base + ko);
                    ldsm_x2(bl, kl_base + ko);
                    mma_bf16(sacc[nb], ah, bh);
                    mma_bf16(sacc[nb], ah, bl);
                    mma_bf16(sacc[nb], al, bh);
                }
            }

            // ---- online softmax on the tile ----
            float t0 = -1e30f, t1 = -1e30f;
#pragma unroll
            for (int nb = 0; nb < 8; nb++) {
                t0 = fmaxf(t0, fmaxf(sacc[nb][0], sacc[nb][1]));
                t1 = fmaxf(t1, fmaxf(sacc[nb][2], sacc[nb][3]));
            }
            t0 = fmaxf(t0, __shfl_xor_sync(0xFFFFFFFFu, t0, 1));
            t0 = fmaxf(t0, __shfl_xor_sync(0xFFFFFFFFu, t0, 2));
            t1 = fmaxf(t1, __shfl_xor_sync(0xFFFFFFFFu, t1, 1));
            t1 = fmaxf(t1, __shfl_xor_sync(0xFFFFFFFFu, t1, 2));

            float nm0 = fmaxf(m0, t0);
            float nm1 = fmaxf(m1, t1);
            float corr0 = __expf(m0 - nm0);
            float corr1 = __expf(m1 - nm1);
            m0 = nm0; m1 = nm1;
            l0 *= corr0; l1 *= corr1;
#pragma unroll
            for (int vb = 0; vb < 10; vb++) {
                oacc[vb][0] *= corr0; oacc[vb][1] *= corr0;
                oacc[vb][2] *= corr1; oacc[vb][3] *= corr1;
            }

            uint32_t ph0[8], ph1[8], pl0[8], pl1[8];
#pragma unroll
            for (int nb = 0; nb < 8; nb++) {
                float p0 = __expf(sacc[nb][0] - m0);
                float p1 = __expf(sacc[nb][1] - m0);
                float p2 = __expf(sacc[nb][2] - m1);
                float p3 = __expf(sacc[nb][3] - m1);
                l0 += p0 + p1;
                l1 += p2 + p3;
                split_pack2(p0, p1, ph0[nb], pl0[nb]);
                split_pack2(p2, p3, ph1[nb], pl1[nb]);
            }

            // ---- O += P V ----
#pragma unroll
            for (int kc = 0; kc < 4; kc++) {
                uint32_t aH[4] = { ph0[2 * kc], ph1[2 * kc], ph0[2 * kc + 1], ph1[2 * kc + 1] };
                uint32_t aL[4] = { pl0[2 * kc], pl1[2 * kc], pl0[2 * kc + 1], pl1[2 * kc + 1] };
#pragma unroll
                for (int vb = 0; vb < 10; vb++) {
                    uint32_t bvh[2], bvl[2];
                    uint32_t vo = (uint32_t)(vb * 8 * AV + kt * 64 + kc * 16) * 2;
                    ldsm_x2(bvh, vh_base + vo);
                    ldsm_x2(bvl, vl_base + vo);
                    mma_bf16(oacc[vb], aH, bvh);
                    mma_bf16(oacc[vb], aH, bvl);
                    mma_bf16(oacc[vb], aL, bvh);
                }
            }
        }

        // ---- finalize: reduce l over quad, normalize, store ----
        l0 += __shfl_xor_sync(0xFFFFFFFFu, l0, 1);
        l0 += __shfl_xor_sync(0xFFFFFFFFu, l0, 2);
        l1 += __shfl_xor_sync(0xFFFFFFFFu, l1, 1);
        l1 += __shfl_xor_sync(0xFFFFFFFFu, l1, 2);
        float inv0 = 1.0f / l0;
        float inv1 = 1.0f / l1;

        int row0 = s0 + qt * 128 + mr + g;
        float* op0 = &out[(size_t)row0 * (N_HEADS * HEAD_DIM) + h * HEAD_DIM + qc * 2];
        float* op1 = &out[(size_t)(row0 + 8) * (N_HEADS * HEAD_DIM) + h * HEAD_DIM + qc * 2];
#pragma unroll
        for (int vb = 0; vb < 10; vb++) {
            float2 a, b;
            a.x = oacc[vb][0] * inv0; a.y = oacc[vb][1] * inv0;
            b.x = oacc[vb][2] * inv1; b.y = oacc[vb][3] * inv1;
            *(float2*)&op0[vb * 8] = a;
            *(float2*)&op1[vb * 8] = b;
        }
    }
}

// ---------------------------------------------------------------------------
// Launcher
// ---------------------------------------------------------------------------
extern "C" void kernel_launch(void* const* d_in, const int* in_sizes, int n_in,
                              void* d_out, int out_size)
{
    const float* x    = (const float*)d_in[0];
    const int*   cu   = (const int*)d_in[1];
    const float* Wqkv = (const float*)d_in[2];
    const float* bqkv = (const float*)d_in[3];
    float* out = (float*)d_out;

    const int nseg = in_sizes[1] - 1;

    float* qkv;
    cudaGetSymbolAddress((void**)&qkv, g_qkv);

    // 0) split x, W into bf16 hi/lo
    split_kernel<<<(NX4 + NW4 + 255) / 256, 256>>>(x, Wqkv);

    // 1) QKV projection (bf16 3-split HMMA, pipelined)
    cudaFuncSetAttribute(qkv_gemm_mma,
                         cudaFuncAttributeMaxDynamicSharedMemorySize, 2 * STAGE_BYTES);
    dim3 g1(N_QKV / GBN, S_LEN / GBM);   // 30 x 16
    qkv_gemm_mma<<<g1, 256, 2 * STAGE_BYTES>>>(bqkv, qkv);

    // 2) block-diagonal flash attention (HMMA)
    cudaFuncSetAttribute(attn_mma,
                         cudaFuncAttributeMaxDynamicSharedMemorySize, ATTN_SMEM);
    dim3 g2(nseg, N_HEADS);
    attn_mma<<<g2, 256, ATTN_SMEM>>>(qkv, cu, out);
}

// round 5
// speedup vs baseline: 3.1922x; 1.2443x over previous
#include <cuda_runtime.h>
#include <cuda_fp16.h>
#include <math.h>
#include <cstdint>

// Problem constants (fixed by the dataset)
#define S_LEN 2048
#define D_MODEL 1280
#define N_QKV 3840
#define N_HEADS 16
#define HEAD_DIM 80
#define SEG_LEN 256

// Global scratch
__device__ float g_qkv[S_LEN * N_QKV];
__device__ __half g_xh[S_LEN * D_MODEL];
__device__ __half g_xl[S_LEN * D_MODEL];
__device__ __half g_wh[N_QKV * D_MODEL];

// ---------------------------------------------------------------------------
// Helpers
// ---------------------------------------------------------------------------
__device__ __forceinline__ uint32_t smem_u32(const void* p) {
    uint32_t a;
    asm("{ .reg .u64 t; cvta.to.shared.u64 t, %1; cvt.u32.u64 %0, t; }"
        : "=r"(a) : "l"(p));
    return a;
}
__device__ __forceinline__ void ldsm_x4(uint32_t* r, uint32_t addr) {
    asm volatile("ldmatrix.sync.aligned.m8n8.x4.shared.b16 {%0,%1,%2,%3}, [%4];"
                 : "=r"(r[0]), "=r"(r[1]), "=r"(r[2]), "=r"(r[3]) : "r"(addr));
}
__device__ __forceinline__ void ldsm_x2(uint32_t* r, uint32_t addr) {
    asm volatile("ldmatrix.sync.aligned.m8n8.x2.shared.b16 {%0,%1}, [%2];"
                 : "=r"(r[0]), "=r"(r[1]) : "r"(addr));
}
__device__ __forceinline__ void ldsm_x2_trans(uint32_t* r, uint32_t addr) {
    asm volatile("ldmatrix.sync.aligned.m8n8.x2.trans.shared.b16 {%0,%1}, [%2];"
                 : "=r"(r[0]), "=r"(r[1]) : "r"(addr));
}
__device__ __forceinline__ void mma_f16(float* c, const uint32_t* a, const uint32_t* b) {
    asm volatile(
        "mma.sync.aligned.m16n8k16.row.col.f32.f16.f16.f32 "
        "{%0,%1,%2,%3}, {%4,%5,%6,%7}, {%8,%9}, {%0,%1,%2,%3};"
        : "+f"(c[0]), "+f"(c[1]), "+f"(c[2]), "+f"(c[3])
        : "r"(a[0]), "r"(a[1]), "r"(a[2]), "r"(a[3]), "r"(b[0]), "r"(b[1]));
}
__device__ __forceinline__ void cp16(uint32_t dst, const void* src) {
    asm volatile("cp.async.ca.shared.global [%0], [%1], 16;" :: "r"(dst), "l"(src));
}
#define CP_COMMIT() asm volatile("cp.async.commit_group;" ::: "memory")
#define CP_WAIT1() asm volatile("cp.async.wait_group 1;" ::: "memory")
#define CP_WAIT0() asm volatile("cp.async.wait_group 0;" ::: "memory")

__device__ __forceinline__ void split2h(float v, __half& h, __half& l) {
    h = __float2half(v);
    l = __float2half(v - __half2float(h));
}
__device__ __forceinline__ void split_pack2h(float a, float b, uint32_t& hi, uint32_t& lo) {
    __half ha = __float2half(a), hb = __float2half(b);
    __half2 H = __halves2half2(ha, hb);
    hi = *(uint32_t*)&H;
    __half la = __float2half(a - __half2float(ha));
    __half lb = __float2half(b - __half2float(hb));
    __half2 L2 = __halves2half2(la, lb);
    lo = *(uint32_t*)&L2;
}

// ---------------------------------------------------------------------------
// Kernel 0: split x -> fp16 hi/lo; round W -> fp16 hi
// ---------------------------------------------------------------------------
#define NX4 (S_LEN * D_MODEL / 4)   // 655360
#define NW4 (N_QKV * D_MODEL / 4)   // 1228800

__global__ __launch_bounds__(256) void split_kernel(
    const float* __restrict__ x, const float* __restrict__ w)
{
    int i = blockIdx.x * blockDim.x + threadIdx.x;
    if (i >= NX4 + NW4) return;
    if (i < NX4) {
        float4 v = ((const float4*)x)[i];
        __half hx, hy, hz, hw, lx, ly, lz, lw;
        split2h(v.x, hx, lx); split2h(v.y, hy, ly);
        split2h(v.z, hz, lz); split2h(v.w, hw, lw);
        __half2 a = __halves2half2(hx, hy), b = __halves2half2(hz, hw);
        uint2 H; H.x = *(uint32_t*)&a; H.y = *(uint32_t*)&b;
        ((uint2*)g_xh)[i] = H;
        a = __halves2half2(lx, ly); b = __halves2half2(lz, lw);
        uint2 L; L.x = *(uint32_t*)&a; L.y = *(uint32_t*)&b;
        ((uint2*)g_xl)[i] = L;
    } else {
        int off = i - NX4;
        float4 v = ((const float4*)w)[off];
        __half2 a = __halves2half2(__float2half(v.x), __float2half(v.y));
        __half2 b = __halves2half2(__float2half(v.z), __float2half(v.w));
        uint2 H; H.x = *(uint32_t*)&a; H.y = *(uint32_t*)&b;
        ((uint2*)g_wh)[off] = H;
    }
}

// ---------------------------------------------------------------------------
// Kernel 1: QKV GEMM, fp16 2-pass (split-A, round-B), cp.async double-buffered
// ---------------------------------------------------------------------------
#define GBM 128
#define GBN 128
#define GBK 32
#define NCHUNK (D_MODEL / GBK)   // 40
#define AST 40                   // smem row stride (halfs) = 80 B, conflict-free
#define ARR_BYTES (128 * AST * 2)        // 10240
#define STAGE_BYTES (3 * ARR_BYTES)      // 30720

__global__ __launch_bounds__(256, 2) void qkv_gemm_mma(
    const float* __restrict__ bias,
    float* __restrict__ C)
{
    extern __shared__ char smem[];
    const uint32_t sb = smem_u32(smem);

    const int tid = threadIdx.x;
    const int wid = tid >> 5;
    const int lane = tid & 31;
    const int wm = wid >> 2;
    const int wn = wid & 3;
    const int bn = blockIdx.x * GBN;
    const int bm = blockIdx.y * GBM;

    float acc[4][4][4];
#pragma unroll
    for (int i = 0; i < 4; i++)
#pragma unroll
        for (int j = 0; j < 4; j++)
#pragma unroll
            for (int k = 0; k < 4; k++) acc[i][j][k] = 0.0f;

    const int lr = lane & 7;
    const int lsub = lane >> 3;
    const int a_row_off = (lsub & 1) * 8 + lr;
    const int a_k_off = (lsub >> 1) * 8;
    const int b_k_off = (lsub & 1) * 8;

    // stage loader: per array 512 16B-chunks, 2 per thread
    auto load_stage = [&](int c, int st) {
        uint32_t dbase = sb + st * STAGE_BYTES;
        size_t k0 = (size_t)c * GBK;
#pragma unroll
        for (int i = 0; i < 2; i++) {
            int id = i * 256 + tid;
            int row = id >> 2, ch = id & 3;
            uint32_t d = dbase + (uint32_t)(row * AST + ch * 8) * 2;
            size_t so = k0 + ch * 8;
            cp16(d + 0 * ARR_BYTES, g_xh + (size_t)(bm + row) * D_MODEL + so);
            cp16(d + 1 * ARR_BYTES, g_xl + (size_t)(bm + row) * D_MODEL + so);
            cp16(d + 2 * ARR_BYTES, g_wh + (size_t)(bn + row) * D_MODEL + so);
        }
        CP_COMMIT();
    };

    load_stage(0, 0);

    for (int c = 0; c < NCHUNK; c++) {
        const int cur = c & 1;
        if (c + 1 < NCHUNK) {
            load_stage(c + 1, cur ^ 1);
            CP_WAIT1();
        } else {
            CP_WAIT0();
        }
        __syncthreads();

        const uint32_t sAh = sb + cur * STAGE_BYTES;
        const uint32_t sAl = sAh + ARR_BYTES;
        const uint32_t sBh = sAh + 2 * ARR_BYTES;

#pragma unroll
        for (int ks = 0; ks < 2; ks++) {
            uint32_t ah[4][4], al[4][4];
#pragma unroll
            for (int mb = 0; mb < 4; mb++) {
                uint32_t off = (uint32_t)((wm * 64 + mb * 16 + a_row_off) * AST
                                          + ks * 16 + a_k_off) * 2;
                ldsm_x4(ah[mb], sAh + off);
                ldsm_x4(al[mb], sAl + off);
            }
#pragma unroll
            for (int nb = 0; nb < 4; nb++) {
                uint32_t bh[2];
                uint32_t off = (uint32_t)((wn * 32 + nb * 8 + lr) * AST
                                          + ks * 16 + b_k_off) * 2;
                ldsm_x2(bh, sBh + off);
#pragma unroll
                for (int mb = 0; mb < 4; mb++) {
                    mma_f16(acc[mb][nb], ah[mb], bh);
                    mma_f16(acc[mb][nb], al[mb], bh);
                }
            }
        }
        __syncthreads();
    }

    const int g = lane >> 2;
    const int cc = lane & 3;
#pragma unroll
    for (int mb = 0; mb < 4; mb++) {
#pragma unroll
        for (int nb = 0; nb < 4; nb++) {
            int row = bm + wm * 64 + mb * 16 + g;
            int col = bn + wn * 32 + nb * 8 + cc * 2;
            float2 bv = *(const float2*)&bias[col];
            float2 o0, o1;
            o0.x = acc[mb][nb][0] + bv.x;
            o0.y = acc[mb][nb][1] + bv.y;
            o1.x = acc[mb][nb][2] + bv.x;
            o1.y = acc[mb][nb][3] + bv.y;
            *(float2*)&C[(size_t)row * N_QKV + col] = o0;
            *(float2*)&C[(size_t)(row + 8) * N_QKV + col] = o1;
        }
    }
}

// ---------------------------------------------------------------------------
// Kernel 2: block-diagonal flash attention, fp16 2-pass.
// Q split hi/lo; K,V rounded to fp16, both row-major. V fragments via
// ldmatrix.trans. One CTA per (segment, head); warp owns 16 q-rows; 2 Q tiles.
// ---------------------------------------------------------------------------
#define AK 88    // row stride (halfs): 176 B, conflict-free

#define OFF_QH 0
#define OFF_QL (OFF_QH + 128 * AK * 2)   // 22528
#define OFF_KH (OFF_QL + 128 * AK * 2)   // 45056
#define OFF_VH (OFF_KH + 256 * AK * 2)   // 90112
#define ATTN_SMEM (OFF_VH + 256 * AK * 2) // 135168

__global__ __launch_bounds__(256, 1) void attn_mma(
    const float* __restrict__ qkv,
    const int* __restrict__ cu_seqlens,
    float* __restrict__ out)
{
    extern __shared__ char smem[];
    const uint32_t sb = smem_u32(smem);
    __half* Qh = (__half*)(smem + OFF_QH);
    __half* Ql = (__half*)(smem + OFF_QL);
    __half* Kh = (__half*)(smem + OFF_KH);
    __half* Vh = (__half*)(smem + OFF_VH);

    const int seg = blockIdx.x;
    const int h = blockIdx.y;
    const int s0 = cu_seqlens[seg];

    const int tid = threadIdx.x;
    const int wid = tid >> 5;
    const int lane = tid & 31;
    const int lr = lane & 7;
    const int lsub = lane >> 3;
    const int a_row_off = (lsub & 1) * 8 + lr;
    const int a_k_off = (lsub >> 1) * 8;
    const int b_k_off = (lsub & 1) * 8;
    const int v_row_off = (lsub & 1) * 8 + lr;   // trans-ldsm row within k16
    const int g = lane >> 2;
    const int qc = lane & 3;
    const int mr = wid * 16;

    const float scale = 0.111803398874989485f;  // 1/sqrt(80)

    // ---- load K, V (round to fp16, row-major) ----
    for (int i = tid; i < SEG_LEN * HEAD_DIM; i += 256) {
        int kv = i / HEAD_DIM;
        int d = i - kv * HEAD_DIM;
        size_t base = (size_t)(s0 + kv) * N_QKV + h * HEAD_DIM + d;
        Kh[kv * AK + d] = __float2half(qkv[base + D_MODEL]);
        Vh[kv * AK + d] = __float2half(qkv[base + 2 * D_MODEL]);
    }
    // ---- load Q tile 0 (scaled, split hi/lo) ----
    for (int i = tid; i < 128 * HEAD_DIM; i += 256) {
        int r = i / HEAD_DIM;
        int d = i - r * HEAD_DIM;
        float v = qkv[(size_t)(s0 + r) * N_QKV + h * HEAD_DIM + d] * scale;
        __half hh, ll;
        split2h(v, hh, ll);
        Qh[r * AK + d] = hh;
        Ql[r * AK + d] = ll;
    }
    __syncthreads();

    const uint32_t qh_base = sb + OFF_QH + (uint32_t)((mr + a_row_off) * AK + a_k_off) * 2;
    const uint32_t ql_base = sb + OFF_QL + (uint32_t)((mr + a_row_off) * AK + a_k_off) * 2;
    const uint32_t kh_base = sb + OFF_KH + (uint32_t)(lr * AK + b_k_off) * 2;
    const uint32_t vh_base = sb + OFF_VH + (uint32_t)(v_row_off * AK) * 2;

    for (int qt = 0; qt < 2; qt++) {
        if (qt) {
            __syncthreads();
            for (int i = tid; i < 128 * HEAD_DIM; i += 256) {
                int r = i / HEAD_DIM;
                int d = i - r * HEAD_DIM;
                float v = qkv[(size_t)(s0 + 128 + r) * N_QKV + h * HEAD_DIM + d] * scale;
                __half hh, ll;
                split2h(v, hh, ll);
                Qh[r * AK + d] = hh;
                Ql[r * AK + d] = ll;
            }
            __syncthreads();
        }

        float oacc[10][4];
#pragma unroll
        for (int vb = 0; vb < 10; vb++)
#pragma unroll
            for (int k = 0; k < 4; k++) oacc[vb][k] = 0.0f;
        float m0 = -1e30f, m1 = -1e30f, l0 = 0.0f, l1 = 0.0f;

        for (int kt = 0; kt < 4; kt++) {
            // ---- S = Q K^T on this 64-wide KV tile ----
            float sacc[8][4];
#pragma unroll
            for (int nb = 0; nb < 8; nb++)
#pragma unroll
                for (int k = 0; k < 4; k++) sacc[nb][k] = 0.0f;

#pragma unroll
            for (int kb = 0; kb < 5; kb++) {
                uint32_t ah[4], al[4];
                ldsm_x4(ah, qh_base + kb * 32);
                ldsm_x4(al, ql_base + kb * 32);
#pragma unroll
                for (int nb = 0; nb < 8; nb++) {
                    uint32_t bh[2];
                    uint32_t ko = (uint32_t)((kt * 64 + nb * 8) * AK + kb * 16) * 2;
                    ldsm_x2(bh, kh_base + ko);
                    mma_f16(sacc[nb], ah, bh);
                    mma_f16(sacc[nb], al, bh);
                }
            }

            // ---- online softmax on the tile ----
            float t0 = -1e30f, t1 = -1e30f;
#pragma unroll
            for (int nb = 0; nb < 8; nb++) {
                t0 = fmaxf(t0, fmaxf(sacc[nb][0], sacc[nb][1]));
                t1 = fmaxf(t1, fmaxf(sacc[nb][2], sacc[nb][3]));
            }
            t0 = fmaxf(t0, __shfl_xor_sync(0xFFFFFFFFu, t0, 1));
            t0 = fmaxf(t0, __shfl_xor_sync(0xFFFFFFFFu, t0, 2));
            t1 = fmaxf(t1, __shfl_xor_sync(0xFFFFFFFFu, t1, 1));
            t1 = fmaxf(t1, __shfl_xor_sync(0xFFFFFFFFu, t1, 2));

            float nm0 = fmaxf(m0, t0);
            float nm1 = fmaxf(m1, t1);
            float corr0 = __expf(m0 - nm0);
            float corr1 = __expf(m1 - nm1);
            m0 = nm0; m1 = nm1;
            l0 *= corr0; l1 *= corr1;
#pragma unroll
            for (int vb = 0; vb < 10; vb++) {
                oacc[vb][0] *= corr0; oacc[vb][1] *= corr0;
                oacc[vb][2] *= corr1; oacc[vb][3] *= corr1;
            }

            uint32_t ph0[8], ph1[8], pl0[8], pl1[8];
#pragma unroll
            for (int nb = 0; nb < 8; nb++) {
                float p0 = __expf(sacc[nb][0] - m0);
                float p1 = __expf(sacc[nb][1] - m0);
                float p2 = __expf(sacc[nb][2] - m1);
                float p3 = __expf(sacc[nb][3] - m1);
                l0 += p0 + p1;
                l1 += p2 + p3;
                split_pack2h(p0, p1, ph0[nb], pl0[nb]);
                split_pack2h(p2, p3, ph1[nb], pl1[nb]);
            }

            // ---- O += P V  (V fragments via ldmatrix.trans) ----
#pragma unroll
            for (int kc = 0; kc < 4; kc++) {
                uint32_t aH[4] = { ph0[2 * kc], ph1[2 * kc], ph0[2 * kc + 1], ph1[2 * kc + 1] };
                uint32_t aL[4] = { pl0[2 * kc], pl1[2 * kc], pl0[2 * kc + 1], pl1[2 * kc + 1] };
                uint32_t vrow = vh_base + (uint32_t)((kt * 64 + kc * 16) * AK) * 2;
#pragma unroll
                for (int vb = 0; vb < 10; vb++) {
                    uint32_t bvh[2];
                    ldsm_x2_trans(bvh, vrow + vb * 16);
                    mma_f16(oacc[vb], aH, bvh);
                    mma_f16(oacc[vb], aL, bvh);
                }
            }
        }

        // ---- finalize ----
        l0 += __shfl_xor_sync(0xFFFFFFFFu, l0, 1);
        l0 += __shfl_xor_sync(0xFFFFFFFFu, l0, 2);
        l1 += __shfl_xor_sync(0xFFFFFFFFu, l1, 1);
        l1 += __shfl_xor_sync(0xFFFFFFFFu, l1, 2);
        float inv0 = 1.0f / l0;
        float inv1 = 1.0f / l1;

        int row0 = s0 + qt * 128 + mr + g;
        float* op0 = &out[(size_t)row0 * (N_HEADS * HEAD_DIM) + h * HEAD_DIM + qc * 2];
        float* op1 = &out[(size_t)(row0 + 8) * (N_HEADS * HEAD_DIM) + h * HEAD_DIM + qc * 2];
#pragma unroll
        for (int vb = 0; vb < 10; vb++) {
            float2 a, b;
            a.x = oacc[vb][0] * inv0; a.y = oacc[vb][1] * inv0;
            b.x = oacc[vb][2] * inv1; b.y = oacc[vb][3] * inv1;
            *(float2*)&op0[vb * 8] = a;
            *(float2*)&op1[vb * 8] = b;
        }
    }
}

// ---------------------------------------------------------------------------
// Launcher
// ---------------------------------------------------------------------------
extern "C" void kernel_launch(void* const* d_in, const int* in_sizes, int n_in,
                              void* d_out, int out_size)
{
    const float* x    = (const float*)d_in[0];
    const int*   cu   = (const int*)d_in[1];
    const float* Wqkv = (const float*)d_in[2];
    const float* bqkv = (const float*)d_in[3];
    float* out = (float*)d_out;

    const int nseg = in_sizes[1] - 1;

    float* qkv;
    cudaGetSymbolAddress((void**)&qkv, g_qkv);

    // 0) split x -> fp16 hi/lo; round W -> fp16
    split_kernel<<<(NX4 + NW4 + 255) / 256, 256>>>(x, Wqkv);

    // 1) QKV projection (fp16 2-pass HMMA, double-buffered, occ 2)
    cudaFuncSetAttribute(qkv_gemm_mma,
                         cudaFuncAttributeMaxDynamicSharedMemorySize, 2 * STAGE_BYTES);
    dim3 g1(N_QKV / GBN, S_LEN / GBM);   // 30 x 16
    qkv_gemm_mma<<<g1, 256, 2 * STAGE_BYTES>>>(bqkv, qkv);

    // 2) block-diagonal flash attention (fp16 2-pass HMMA)
    cudaFuncSetAttribute(attn_mma,
                         cudaFuncAttributeMaxDynamicSharedMemorySize, ATTN_SMEM);
    dim3 g2(nseg, N_HEADS);
    attn_mma<<<g2, 256, ATTN_SMEM>>>(qkv, cu, out);
}

// round 6
// speedup vs baseline: 3.7597x; 1.1778x over previous
#include <cuda_runtime.h>
#include <cuda_fp16.h>
#include <math.h>
#include <cstdint>

// Problem constants (fixed by the dataset)
#define S_LEN 2048
#define D_MODEL 1280
#define N_QKV 3840
#define N_HEADS 16
#define HEAD_DIM 80
#define SEG_LEN 256

// Global scratch: GEMM inputs (split) and GEMM outputs in attention layout
__device__ __half g_xh[S_LEN * D_MODEL];
__device__ __half g_xl[S_LEN * D_MODEL];
__device__ __half g_wh[N_QKV * D_MODEL];
// [head][s][d] fp16
__device__ __half g_qh[N_HEADS * S_LEN * HEAD_DIM];
__device__ __half g_ql[N_HEADS * S_LEN * HEAD_DIM];
__device__ __half g_kh[N_HEADS * S_LEN * HEAD_DIM];
__device__ __half g_vh[N_HEADS * S_LEN * HEAD_DIM];

// ---------------------------------------------------------------------------
// Helpers
// ---------------------------------------------------------------------------
__device__ __forceinline__ uint32_t smem_u32(const void* p) {
    uint32_t a;
    asm("{ .reg .u64 t; cvta.to.shared.u64 t, %1; cvt.u32.u64 %0, t; }"
        : "=r"(a) : "l"(p));
    return a;
}
__device__ __forceinline__ void ldsm_x4(uint32_t* r, uint32_t addr) {
    asm volatile("ldmatrix.sync.aligned.m8n8.x4.shared.b16 {%0,%1,%2,%3}, [%4];"
                 : "=r"(r[0]), "=r"(r[1]), "=r"(r[2]), "=r"(r[3]) : "r"(addr));
}
__device__ __forceinline__ void ldsm_x2(uint32_t* r, uint32_t addr) {
    asm volatile("ldmatrix.sync.aligned.m8n8.x2.shared.b16 {%0,%1}, [%2];"
                 : "=r"(r[0]), "=r"(r[1]) : "r"(addr));
}
__device__ __forceinline__ void ldsm_x2_trans(uint32_t* r, uint32_t addr) {
    asm volatile("ldmatrix.sync.aligned.m8n8.x2.trans.shared.b16 {%0,%1}, [%2];"
                 : "=r"(r[0]), "=r"(r[1]) : "r"(addr));
}
__device__ __forceinline__ void mma_f16(float* c, const uint32_t* a, const uint32_t* b) {
    asm volatile(
        "mma.sync.aligned.m16n8k16.row.col.f32.f16.f16.f32 "
        "{%0,%1,%2,%3}, {%4,%5,%6,%7}, {%8,%9}, {%0,%1,%2,%3};"
        : "+f"(c[0]), "+f"(c[1]), "+f"(c[2]), "+f"(c[3])
        : "r"(a[0]), "r"(a[1]), "r"(a[2]), "r"(a[3]), "r"(b[0]), "r"(b[1]));
}
__device__ __forceinline__ void cp16(uint32_t dst, const void* src) {
    asm volatile("cp.async.ca.shared.global [%0], [%1], 16;" :: "r"(dst), "l"(src));
}
#define CP_COMMIT() asm volatile("cp.async.commit_group;" ::: "memory")
#define CP_WAIT1() asm volatile("cp.async.wait_group 1;" ::: "memory")
#define CP_WAIT0() asm volatile("cp.async.wait_group 0;" ::: "memory")

__device__ __forceinline__ void split2h(float v, __half& h, __half& l) {
    h = __float2half(v);
    l = __float2half(v - __half2float(h));
}

// ---------------------------------------------------------------------------
// Kernel 0: split x -> fp16 hi/lo; round W -> fp16 hi
// ---------------------------------------------------------------------------
#define NX4 (S_LEN * D_MODEL / 4)   // 655360
#define NW4 (N_QKV * D_MODEL / 4)   // 1228800

__global__ __launch_bounds__(256) void split_kernel(
    const float* __restrict__ x, const float* __restrict__ w)
{
    int i = blockIdx.x * blockDim.x + threadIdx.x;
    if (i >= NX4 + NW4) return;
    if (i < NX4) {
        float4 v = ((const float4*)x)[i];
        __half hx, hy, hz, hw, lx, ly, lz, lw;
        split2h(v.x, hx, lx); split2h(v.y, hy, ly);
        split2h(v.z, hz, lz); split2h(v.w, hw, lw);
        __half2 a = __halves2half2(hx, hy), b = __halves2half2(hz, hw);
        uint2 H; H.x = *(uint32_t*)&a; H.y = *(uint32_t*)&b;
        ((uint2*)g_xh)[i] = H;
        a = __halves2half2(lx, ly); b = __halves2half2(lz, lw);
        uint2 L; L.x = *(uint32_t*)&a; L.y = *(uint32_t*)&b;
        ((uint2*)g_xl)[i] = L;
    } else {
        int off = i - NX4;
        float4 v = ((const float4*)w)[off];
        __half2 a = __halves2half2(__float2half(v.x), __float2half(v.y));
        __half2 b = __halves2half2(__float2half(v.z), __float2half(v.w));
        uint2 H; H.x = *(uint32_t*)&a; H.y = *(uint32_t*)&b;
        ((uint2*)g_wh)[off] = H;
    }
}

// ---------------------------------------------------------------------------
// Kernel 1: QKV GEMM, fp16 2-pass (split-A, round-B), cp.async double-buffered.
// Epilogue writes Q (scaled, split hi/lo), K, V directly as fp16 [h][s][d].
// ---------------------------------------------------------------------------
#define GBM 128
#define GBN 128
#define GBK 32
#define NCHUNK (D_MODEL / GBK)   // 40
#define AST 40                   // smem row stride (halfs) = 80 B, conflict-free
#define ARR_BYTES (128 * AST * 2)        // 10240
#define STAGE_BYTES (3 * ARR_BYTES)      // 30720

__global__ __launch_bounds__(256, 2) void qkv_gemm_mma(
    const float* __restrict__ bias)
{
    extern __shared__ char smem[];
    const uint32_t sb = smem_u32(smem);

    const int tid = threadIdx.x;
    const int wid = tid >> 5;
    const int lane = tid & 31;
    const int wm = wid >> 2;
    const int wn = wid & 3;
    const int bn = blockIdx.x * GBN;
    const int bm = blockIdx.y * GBM;

    float acc[4][4][4];
#pragma unroll
    for (int i = 0; i < 4; i++)
#pragma unroll
        for (int j = 0; j < 4; j++)
#pragma unroll
            for (int k = 0; k < 4; k++) acc[i][j][k] = 0.0f;

    const int lr = lane & 7;
    const int lsub = lane >> 3;
    const int a_row_off = (lsub & 1) * 8 + lr;
    const int a_k_off = (lsub >> 1) * 8;
    const int b_k_off = (lsub & 1) * 8;

    auto load_stage = [&](int c, int st) {
        uint32_t dbase = sb + st * STAGE_BYTES;
        size_t k0 = (size_t)c * GBK;
#pragma unroll
        for (int i = 0; i < 2; i++) {
            int id = i * 256 + tid;
            int row = id >> 2, ch = id & 3;
            uint32_t d = dbase + (uint32_t)(row * AST + ch * 8) * 2;
            size_t so = k0 + ch * 8;
            cp16(d + 0 * ARR_BYTES, g_xh + (size_t)(bm + row) * D_MODEL + so);
            cp16(d + 1 * ARR_BYTES, g_xl + (size_t)(bm + row) * D_MODEL + so);
            cp16(d + 2 * ARR_BYTES, g_wh + (size_t)(bn + row) * D_MODEL + so);
        }
        CP_COMMIT();
    };

    load_stage(0, 0);

    for (int c = 0; c < NCHUNK; c++) {
        const int cur = c & 1;
        if (c + 1 < NCHUNK) {
            load_stage(c + 1, cur ^ 1);
            CP_WAIT1();
        } else {
            CP_WAIT0();
        }
        __syncthreads();

        const uint32_t sAh = sb + cur * STAGE_BYTES;
        const uint32_t sAl = sAh + ARR_BYTES;
        const uint32_t sBh = sAh + 2 * ARR_BYTES;

#pragma unroll
        for (int ks = 0; ks < 2; ks++) {
            uint32_t ah[4][4], al[4][4];
#pragma unroll
            for (int mb = 0; mb < 4; mb++) {
                uint32_t off = (uint32_t)((wm * 64 + mb * 16 + a_row_off) * AST
                                          + ks * 16 + a_k_off) * 2;
                ldsm_x4(ah[mb], sAh + off);
                ldsm_x4(al[mb], sAl + off);
            }
#pragma unroll
            for (int nb = 0; nb < 4; nb++) {
                uint32_t bh[2];
                uint32_t off = (uint32_t)((wn * 32 + nb * 8 + lr) * AST
                                          + ks * 16 + b_k_off) * 2;
                ldsm_x2(bh, sBh + off);
#pragma unroll
                for (int mb = 0; mb < 4; mb++) {
                    mma_f16(acc[mb][nb], ah[mb], bh);
                    mma_f16(acc[mb][nb], al[mb], bh);
                }
            }
        }
        __syncthreads();
    }

    // epilogue: bias add, route to Q(scaled, split)/K/V fp16 [h][s][d]
    const float scale = 0.111803398874989485f;  // 1/sqrt(80)
    const int g = lane >> 2;
    const int cc = lane & 3;
#pragma unroll
    for (int nb = 0; nb < 4; nb++) {
        int col = bn + wn * 32 + nb * 8 + cc * 2;
        int sec = col / D_MODEL;          // 0=q 1=k 2=v
        int f = col - sec * D_MODEL;
        int h = f / HEAD_DIM;
        int d = f - h * HEAD_DIM;
        float2 bv = *(const float2*)&bias[col];
        size_t hb = (size_t)h * S_LEN * HEAD_DIM + d;
#pragma unroll
        for (int mb = 0; mb < 4; mb++) {
#pragma unroll
            for (int rr = 0; rr < 2; rr++) {
                int row = bm + wm * 64 + mb * 16 + g + rr * 8;
                float v0 = acc[mb][nb][rr * 2 + 0] + bv.x;
                float v1 = acc[mb][nb][rr * 2 + 1] + bv.y;
                size_t idx = hb + (size_t)row * HEAD_DIM;
                if (sec == 0) {
                    v0 *= scale; v1 *= scale;
                    __half h0, l0h, h1, l1h;
                    split2h(v0, h0, l0h);
                    split2h(v1, h1, l1h);
                    *(__half2*)&g_qh[idx] = __halves2half2(h0, h1);
                    *(__half2*)&g_ql[idx] = __halves2half2(l0h, l1h);
                } else if (sec == 1) {
                    *(__half2*)&g_kh[idx] = __floats2half2_rn(v0, v1);
                } else {
                    *(__half2*)&g_vh[idx] = __floats2half2_rn(v0, v1);
                }
            }
        }
    }
}

// ---------------------------------------------------------------------------
// Kernel 2: block-diagonal flash attention, fp16.
// All tiles (Q hi/lo both 128-row tiles, K, V) cp.async'd upfront (180 KB).
// QK^T: 2-pass (Q split); PV: 1-pass (P rounded to fp16). V via ldmatrix.trans.
// ---------------------------------------------------------------------------
#define AK 88    // row stride (halfs): 176 B, conflict-free

#define OFF_QH 0
#define OFF_QL (OFF_QH + 256 * AK * 2)    // 45056
#define OFF_KH (OFF_QL + 256 * AK * 2)    // 90112
#define OFF_VH (OFF_KH + 256 * AK * 2)    // 135168
#define ATTN_SMEM (OFF_VH + 256 * AK * 2) // 180224

__global__ __launch_bounds__(256, 1) void attn_mma(
    const int* __restrict__ cu_seqlens,
    float* __restrict__ out)
{
    extern __shared__ char smem[];
    const uint32_t sb = smem_u32(smem);

    const int seg = blockIdx.x;
    const int h = blockIdx.y;
    const int s0 = cu_seqlens[seg];

    const int tid = threadIdx.x;
    const int wid = tid >> 5;
    const int lane = tid & 31;
    const int lr = lane & 7;
    const int lsub = lane >> 3;
    const int a_row_off = (lsub & 1) * 8 + lr;
    const int a_k_off = (lsub >> 1) * 8;
    const int b_k_off = (lsub & 1) * 8;
    const int g = lane >> 2;
    const int qc = lane & 3;
    const int mr = wid * 16;

    // ---- cp.async all tiles: thread tid handles smem row tid (10 chunks each) ----
    {
        const size_t hbase = (size_t)h * S_LEN * HEAD_DIM + (size_t)s0 * HEAD_DIM;
        const __half* srcq = g_qh + hbase + tid * HEAD_DIM;
        const __half* srcl = g_ql + hbase + tid * HEAD_DIM;
        const __half* srck = g_kh + hbase + tid * HEAD_DIM;
        const __half* srcv = g_vh + hbase + tid * HEAD_DIM;
        uint32_t drow = sb + (uint32_t)(tid * AK) * 2;
#pragma unroll
        for (int c = 0; c < 10; c++) {
            cp16(drow + OFF_QH + c * 16, srcq + c * 8);
            cp16(drow + OFF_QL + c * 16, srcl + c * 8);
            cp16(drow + OFF_KH + c * 16, srck + c * 8);
            cp16(drow + OFF_VH + c * 16, srcv + c * 8);
        }
        CP_COMMIT();
    }
    CP_WAIT0();
    __syncthreads();

    const uint32_t kh_base = sb + OFF_KH + (uint32_t)(lr * AK + b_k_off) * 2;
    const uint32_t vh_base = sb + OFF_VH + (uint32_t)(a_row_off * AK) * 2;

    for (int qt = 0; qt < 2; qt++) {
        const uint32_t qh_base = sb + OFF_QH
            + (uint32_t)((qt * 128 + mr + a_row_off) * AK + a_k_off) * 2;
        const uint32_t ql_base = sb + OFF_QL
            + (uint32_t)((qt * 128 + mr + a_row_off) * AK + a_k_off) * 2;

        float oacc[10][4];
#pragma unroll
        for (int vb = 0; vb < 10; vb++)
#pragma unroll
            for (int k = 0; k < 4; k++) oacc[vb][k] = 0.0f;
        float m0 = -1e30f, m1 = -1e30f, l0 = 0.0f, l1 = 0.0f;

        for (int kt = 0; kt < 4; kt++) {
            // ---- S = Q K^T on this 64-wide KV tile (2-pass) ----
            float sacc[8][4];
#pragma unroll
            for (int nb = 0; nb < 8; nb++)
#pragma unroll
                for (int k = 0; k < 4; k++) sacc[nb][k] = 0.0f;

#pragma unroll
            for (int kb = 0; kb < 5; kb++) {
                uint32_t ah[4], al[4];
                ldsm_x4(ah, qh_base + kb * 32);
                ldsm_x4(al, ql_base + kb * 32);
#pragma unroll
                for (int nb = 0; nb < 8; nb++) {
                    uint32_t bh[2];
                    uint32_t ko = (uint32_t)((kt * 64 + nb * 8) * AK + kb * 16) * 2;
                    ldsm_x2(bh, kh_base + ko);
                    mma_f16(sacc[nb], ah, bh);
                    mma_f16(sacc[nb], al, bh);
                }
            }

            // ---- online softmax ----
            float t0 = -1e30f, t1 = -1e30f;
#pragma unroll
            for (int nb = 0; nb < 8; nb++) {
                t0 = fmaxf(t0, fmaxf(sacc[nb][0], sacc[nb][1]));
                t1 = fmaxf(t1, fmaxf(sacc[nb][2], sacc[nb][3]));
            }
            t0 = fmaxf(t0, __shfl_xor_sync(0xFFFFFFFFu, t0, 1));
            t0 = fmaxf(t0, __shfl_xor_sync(0xFFFFFFFFu, t0, 2));
            t1 = fmaxf(t1, __shfl_xor_sync(0xFFFFFFFFu, t1, 1));
            t1 = fmaxf(t1, __shfl_xor_sync(0xFFFFFFFFu, t1, 2));

            float nm0 = fmaxf(m0, t0);
            float nm1 = fmaxf(m1, t1);
            float corr0 = __expf(m0 - nm0);
            float corr1 = __expf(m1 - nm1);
            m0 = nm0; m1 = nm1;
            l0 *= corr0; l1 *= corr1;
#pragma unroll
            for (int vb = 0; vb < 10; vb++) {
                oacc[vb][0] *= corr0; oacc[vb][1] *= corr0;
                oacc[vb][2] *= corr1; oacc[vb][3] *= corr1;
            }

            uint32_t ph0[8], ph1[8];
#pragma unroll
            for (int nb = 0; nb < 8; nb++) {
                float p0 = __expf(sacc[nb][0] - m0);
                float p1 = __expf(sacc[nb][1] - m0);
                float p2 = __expf(sacc[nb][2] - m1);
                float p3 = __expf(sacc[nb][3] - m1);
                l0 += p0 + p1;
                l1 += p2 + p3;
                __half2 a = __floats2half2_rn(p0, p1);
                __half2 b = __floats2half2_rn(p2, p3);
                ph0[nb] = *(uint32_t*)&a;
                ph1[nb] = *(uint32_t*)&b;
            }

            // ---- O += P V (1-pass, V via ldmatrix.trans) ----
#pragma unroll
            for (int kc = 0; kc < 4; kc++) {
                uint32_t aH[4] = { ph0[2 * kc], ph1[2 * kc], ph0[2 * kc + 1], ph1[2 * kc + 1] };
                uint32_t vrow = vh_base + (uint32_t)((kt * 64 + kc * 16) * AK) * 2;
#pragma unroll
                for (int vb = 0; vb < 10; vb++) {
                    uint32_t bvh[2];
                    ldsm_x2_trans(bvh, vrow + vb * 16);
                    mma_f16(oacc[vb], aH, bvh);
                }
            }
        }

        // ---- finalize ----
        l0 += __shfl_xor_sync(0xFFFFFFFFu, l0, 1);
        l0 += __shfl_xor_sync(0xFFFFFFFFu, l0, 2);
        l1 += __shfl_xor_sync(0xFFFFFFFFu, l1, 1);
        l1 += __shfl_xor_sync(0xFFFFFFFFu, l1, 2);
        float inv0 = 1.0f / l0;
        float inv1 = 1.0f / l1;

        int row0 = s0 + qt * 128 + mr + g;
        float* op0 = &out[(size_t)row0 * (N_HEADS * HEAD_DIM) + h * HEAD_DIM + qc * 2];
        float* op1 = &out[(size_t)(row0 + 8) * (N_HEADS * HEAD_DIM) + h * HEAD_DIM + qc * 2];
#pragma unroll
        for (int vb = 0; vb < 10; vb++) {
            float2 a, b;
            a.x = oacc[vb][0] * inv0; a.y = oacc[vb][1] * inv0;
            b.x = oacc[vb][2] * inv1; b.y = oacc[vb][3] * inv1;
            *(float2*)&op0[vb * 8] = a;
            *(float2*)&op1[vb * 8] = b;
        }
    }
}

// ---------------------------------------------------------------------------
// Launcher
// ---------------------------------------------------------------------------
extern "C" void kernel_launch(void* const* d_in, const int* in_sizes, int n_in,
                              void* d_out, int out_size)
{
    const float* x    = (const float*)d_in[0];
    const int*   cu   = (const int*)d_in[1];
    const float* Wqkv = (const float*)d_in[2];
    const float* bqkv = (const float*)d_in[3];
    float* out = (float*)d_out;

    const int nseg = in_sizes[1] - 1;

    // 0) split x -> fp16 hi/lo; round W -> fp16
    split_kernel<<<(NX4 + NW4 + 255) / 256, 256>>>(x, Wqkv);

    // 1) QKV projection; epilogue emits fp16 Q(hi/lo)/K/V in [h][s][d]
    cudaFuncSetAttribute(qkv_gemm_mma,
                         cudaFuncAttributeMaxDynamicSharedMemorySize, 2 * STAGE_BYTES);
    dim3 g1(N_QKV / GBN, S_LEN / GBM);   // 30 x 16
    qkv_gemm_mma<<<g1, 256, 2 * STAGE_BYTES>>>(bqkv);

    // 2) block-diagonal flash attention
    cudaFuncSetAttribute(attn_mma,
                         cudaFuncAttributeMaxDynamicSharedMemorySize, ATTN_SMEM);
    dim3 g2(nseg, N_HEADS);
    attn_mma<<<g2, 256, ATTN_SMEM>>>(cu, out);
}

// round 7
// speedup vs baseline: 4.5873x; 1.2201x over previous
#include <cuda_runtime.h>
#include <cuda_fp16.h>
#include <math.h>
#include <cstdint>

// Problem constants (fixed by the dataset)
#define S_LEN 2048
#define D_MODEL 1280
#define N_QKV 3840
#define N_HEADS 16
#define HEAD_DIM 80
#define SEG_LEN 256

// Global scratch: GEMM inputs (split) and GEMM outputs in attention layout
__device__ __half g_xh[S_LEN * D_MODEL];
__device__ __half g_xl[S_LEN * D_MODEL];
__device__ __half g_wh[N_QKV * D_MODEL];
// [head][s][d] fp16
__device__ __half g_qh[N_HEADS * S_LEN * HEAD_DIM];
__device__ __half g_ql[N_HEADS * S_LEN * HEAD_DIM];
__device__ __half g_kh[N_HEADS * S_LEN * HEAD_DIM];
__device__ __half g_vh[N_HEADS * S_LEN * HEAD_DIM];

// ---------------------------------------------------------------------------
// Helpers
// ---------------------------------------------------------------------------
__device__ __forceinline__ uint32_t smem_u32(const void* p) {
    uint32_t a;
    asm("{ .reg .u64 t; cvta.to.shared.u64 t, %1; cvt.u32.u64 %0, t; }"
        : "=r"(a) : "l"(p));
    return a;
}
__device__ __forceinline__ void ldsm_x4(uint32_t* r, uint32_t addr) {
    asm volatile("ldmatrix.sync.aligned.m8n8.x4.shared.b16 {%0,%1,%2,%3}, [%4];"
                 : "=r"(r[0]), "=r"(r[1]), "=r"(r[2]), "=r"(r[3]) : "r"(addr));
}
__device__ __forceinline__ void ldsm_x2(uint32_t* r, uint32_t addr) {
    asm volatile("ldmatrix.sync.aligned.m8n8.x2.shared.b16 {%0,%1}, [%2];"
                 : "=r"(r[0]), "=r"(r[1]) : "r"(addr));
}
__device__ __forceinline__ void ldsm_x2_trans(uint32_t* r, uint32_t addr) {
    asm volatile("ldmatrix.sync.aligned.m8n8.x2.trans.shared.b16 {%0,%1}, [%2];"
                 : "=r"(r[0]), "=r"(r[1]) : "r"(addr));
}
__device__ __forceinline__ void mma_f16(float* c, const uint32_t* a, const uint32_t* b) {
    asm volatile(
        "mma.sync.aligned.m16n8k16.row.col.f32.f16.f16.f32 "
        "{%0,%1,%2,%3}, {%4,%5,%6,%7}, {%8,%9}, {%0,%1,%2,%3};"
        : "+f"(c[0]), "+f"(c[1]), "+f"(c[2]), "+f"(c[3])
        : "r"(a[0]), "r"(a[1]), "r"(a[2]), "r"(a[3]), "r"(b[0]), "r"(b[1]));
}
__device__ __forceinline__ void cp16(uint32_t dst, const void* src) {
    asm volatile("cp.async.ca.shared.global [%0], [%1], 16;" :: "r"(dst), "l"(src));
}
#define CP_COMMIT() asm volatile("cp.async.commit_group;" ::: "memory")
#define CP_WAIT1() asm volatile("cp.async.wait_group 1;" ::: "memory")
#define CP_WAIT0() asm volatile("cp.async.wait_group 0;" ::: "memory")

__device__ __forceinline__ void split2h(float v, __half& h, __half& l) {
    h = __float2half(v);
    l = __float2half(v - __half2float(h));
}

// ---------------------------------------------------------------------------
// Kernel 0: split x -> fp16 hi/lo; round W -> fp16 hi. 8 floats per thread.
// ---------------------------------------------------------------------------
#define NX8 (S_LEN * D_MODEL / 8)   // 327680
#define NW8 (N_QKV * D_MODEL / 8)   // 614400

__global__ __launch_bounds__(256) void split_kernel(
    const float* __restrict__ x, const float* __restrict__ w)
{
    int i = blockIdx.x * blockDim.x + threadIdx.x;
    if (i >= NX8 + NW8) return;
    if (i < NX8) {
        float4 v0 = ((const float4*)x)[2 * i];
        float4 v1 = ((const float4*)x)[2 * i + 1];
        __half h0, h1, h2, h3, h4, h5, h6, h7;
        __half l0, l1, l2, l3, l4, l5, l6, l7;
        split2h(v0.x, h0, l0); split2h(v0.y, h1, l1);
        split2h(v0.z, h2, l2); split2h(v0.w, h3, l3);
        split2h(v1.x, h4, l4); split2h(v1.y, h5, l5);
        split2h(v1.z, h6, l6); split2h(v1.w, h7, l7);
        __half2 p0 = __halves2half2(h0, h1), p1 = __halves2half2(h2, h3);
        __half2 p2 = __halves2half2(h4, h5), p3 = __halves2half2(h6, h7);
        uint4 H;
        H.x = *(uint32_t*)&p0; H.y = *(uint32_t*)&p1;
        H.z = *(uint32_t*)&p2; H.w = *(uint32_t*)&p3;
        ((uint4*)g_xh)[i] = H;
        p0 = __halves2half2(l0, l1); p1 = __halves2half2(l2, l3);
        p2 = __halves2half2(l4, l5); p3 = __halves2half2(l6, l7);
        uint4 L;
        L.x = *(uint32_t*)&p0; L.y = *(uint32_t*)&p1;
        L.z = *(uint32_t*)&p2; L.w = *(uint32_t*)&p3;
        ((uint4*)g_xl)[i] = L;
    } else {
        int off = i - NX8;
        float4 v0 = ((const float4*)w)[2 * off];
        float4 v1 = ((const float4*)w)[2 * off + 1];
        __half2 p0 = __floats2half2_rn(v0.x, v0.y);
        __half2 p1 = __floats2half2_rn(v0.z, v0.w);
        __half2 p2 = __floats2half2_rn(v1.x, v1.y);
        __half2 p3 = __floats2half2_rn(v1.z, v1.w);
        uint4 H;
        H.x = *(uint32_t*)&p0; H.y = *(uint32_t*)&p1;
        H.z = *(uint32_t*)&p2; H.w = *(uint32_t*)&p3;
        ((uint4*)g_wh)[off] = H;
    }
}

// ---------------------------------------------------------------------------
// Kernel 1: QKV GEMM. Q columns (bn<1280): fp16 2-pass (split-A).
// K/V columns: fp16 1-pass (their epilogue rounds to fp16 anyway).
// cp.async double-buffered. Epilogue writes fp16 [h][s][d] directly.
// ---------------------------------------------------------------------------
#define GBM 128
#define GBN 128
#define GBK 32
#define NCHUNK (D_MODEL / GBK)   // 40
#define AST 40                   // smem row stride (halfs) = 80 B, conflict-free
#define ARR_BYTES (128 * AST * 2)        // 10240
#define STAGE_BYTES (3 * ARR_BYTES)      // 30720

__global__ __launch_bounds__(256, 2) void qkv_gemm_mma(
    const float* __restrict__ bias)
{
    extern __shared__ char smem[];
    const uint32_t sb = smem_u32(smem);

    const int tid = threadIdx.x;
    const int wid = tid >> 5;
    const int lane = tid & 31;
    const int wm = wid >> 2;
    const int wn = wid & 3;
    const int bn = blockIdx.x * GBN;
    const int bm = blockIdx.y * GBM;
    const bool needQ = (bn < D_MODEL);   // Q blocks get the lo-correction pass

    float acc[4][4][4];
#pragma unroll
    for (int i = 0; i < 4; i++)
#pragma unroll
        for (int j = 0; j < 4; j++)
#pragma unroll
            for (int k = 0; k < 4; k++) acc[i][j][k] = 0.0f;

    const int lr = lane & 7;
    const int lsub = lane >> 3;
    const int a_row_off = (lsub & 1) * 8 + lr;
    const int a_k_off = (lsub >> 1) * 8;
    const int b_k_off = (lsub & 1) * 8;

    auto load_stage = [&](int c, int st) {
        uint32_t dbase = sb + st * STAGE_BYTES;
        size_t k0 = (size_t)c * GBK;
#pragma unroll
        for (int i = 0; i < 2; i++) {
            int id = i * 256 + tid;
            int row = id >> 2, ch = id & 3;
            uint32_t d = dbase + (uint32_t)(row * AST + ch * 8) * 2;
            size_t so = k0 + ch * 8;
            cp16(d + 0 * ARR_BYTES, g_xh + (size_t)(bm + row) * D_MODEL + so);
            if (needQ)
                cp16(d + 1 * ARR_BYTES, g_xl + (size_t)(bm + row) * D_MODEL + so);
            cp16(d + 2 * ARR_BYTES, g_wh + (size_t)(bn + row) * D_MODEL + so);
        }
        CP_COMMIT();
    };

    load_stage(0, 0);

    for (int c = 0; c < NCHUNK; c++) {
        const int cur = c & 1;
        if (c + 1 < NCHUNK) {
            load_stage(c + 1, cur ^ 1);
            CP_WAIT1();
        } else {
            CP_WAIT0();
        }
        __syncthreads();

        const uint32_t sAh = sb + cur * STAGE_BYTES;
        const uint32_t sAl = sAh + ARR_BYTES;
        const uint32_t sBh = sAh + 2 * ARR_BYTES;

        if (needQ) {
#pragma unroll
            for (int ks = 0; ks < 2; ks++) {
                uint32_t ah[4][4], al[4][4];
#pragma unroll
                for (int mb = 0; mb < 4; mb++) {
                    uint32_t off = (uint32_t)((wm * 64 + mb * 16 + a_row_off) * AST
                                              + ks * 16 + a_k_off) * 2;
                    ldsm_x4(ah[mb], sAh + off);
                    ldsm_x4(al[mb], sAl + off);
                }
#pragma unroll
                for (int nb = 0; nb < 4; nb++) {
                    uint32_t bh[2];
                    uint32_t off = (uint32_t)((wn * 32 + nb * 8 + lr) * AST
                                              + ks * 16 + b_k_off) * 2;
                    ldsm_x2(bh, sBh + off);
#pragma unroll
                    for (int mb = 0; mb < 4; mb++) {
                        mma_f16(acc[mb][nb], ah[mb], bh);
                        mma_f16(acc[mb][nb], al[mb], bh);
                    }
                }
            }
        } else {
#pragma unroll
            for (int ks = 0; ks < 2; ks++) {
                uint32_t ah[4][4];
#pragma unroll
                for (int mb = 0; mb < 4; mb++) {
                    uint32_t off = (uint32_t)((wm * 64 + mb * 16 + a_row_off) * AST
                                              + ks * 16 + a_k_off) * 2;
                    ldsm_x4(ah[mb], sAh + off);
                }
#pragma unroll
                for (int nb = 0; nb < 4; nb++) {
                    uint32_t bh[2];
                    uint32_t off = (uint32_t)((wn * 32 + nb * 8 + lr) * AST
                                              + ks * 16 + b_k_off) * 2;
                    ldsm_x2(bh, sBh + off);
#pragma unroll
                    for (int mb = 0; mb < 4; mb++)
                        mma_f16(acc[mb][nb], ah[mb], bh);
                }
            }
        }
        __syncthreads();
    }

    // epilogue: bias add, route to Q(scaled, split)/K/V fp16 [h][s][d]
    const float scale = 0.111803398874989485f;  // 1/sqrt(80)
    const int g = lane >> 2;
    const int cc = lane & 3;
#pragma unroll
    for (int nb = 0; nb < 4; nb++) {
        int col = bn + wn * 32 + nb * 8 + cc * 2;
        int sec = col / D_MODEL;          // 0=q 1=k 2=v
        int f = col - sec * D_MODEL;
        int h = f / HEAD_DIM;
        int d = f - h * HEAD_DIM;
        float2 bv = *(const float2*)&bias[col];
        size_t hb = (size_t)h * S_LEN * HEAD_DIM + d;
#pragma unroll
        for (int mb = 0; mb < 4; mb++) {
#pragma unroll
            for (int rr = 0; rr < 2; rr++) {
                int row = bm + wm * 64 + mb * 16 + g + rr * 8;
                float v0 = acc[mb][nb][rr * 2 + 0] + bv.x;
                float v1 = acc[mb][nb][rr * 2 + 1] + bv.y;
                size_t idx = hb + (size_t)row * HEAD_DIM;
                if (sec == 0) {
                    v0 *= scale; v1 *= scale;
                    __half h0, l0h, h1, l1h;
                    split2h(v0, h0, l0h);
                    split2h(v1, h1, l1h);
                    *(__half2*)&g_qh[idx] = __halves2half2(h0, h1);
                    *(__half2*)&g_ql[idx] = __halves2half2(l0h, l1h);
                } else if (sec == 1) {
                    *(__half2*)&g_kh[idx] = __floats2half2_rn(v0, v1);
                } else {
                    *(__half2*)&g_vh[idx] = __floats2half2_rn(v0, v1);
                }
            }
        }
    }
}

// ---------------------------------------------------------------------------
// Kernel 2: block-diagonal flash attention, fp16.
// All tiles (Q hi/lo both 128-row tiles, K, V) cp.async'd upfront (180 KB).
// QK^T: 2-pass (Q split); PV: 1-pass (P rounded to fp16). V via ldmatrix.trans.
// ---------------------------------------------------------------------------
#define AK 88    // row stride (halfs): 176 B, conflict-free

#define OFF_QH 0
#define OFF_QL (OFF_QH + 256 * AK * 2)    // 45056
#define OFF_KH (OFF_QL + 256 * AK * 2)    // 90112
#define OFF_VH (OFF_KH + 256 * AK * 2)    // 135168
#define ATTN_SMEM (OFF_VH + 256 * AK * 2) // 180224

__global__ __launch_bounds__(256, 1) void attn_mma(
    const int* __restrict__ cu_seqlens,
    float* __restrict__ out)
{
    extern __shared__ char smem[];
    const uint32_t sb = smem_u32(smem);

    const int seg = blockIdx.x;
    const int h = blockIdx.y;
    const int s0 = cu_seqlens[seg];

    const int tid = threadIdx.x;
    const int wid = tid >> 5;
    const int lane = tid & 31;
    const int lr = lane & 7;
    const int lsub = lane >> 3;
    const int a_row_off = (lsub & 1) * 8 + lr;
    const int a_k_off = (lsub >> 1) * 8;
    const int b_k_off = (lsub & 1) * 8;
    const int g = lane >> 2;
    const int qc = lane & 3;
    const int mr = wid * 16;

    // ---- cp.async all tiles: thread tid handles smem row tid (10 chunks each) ----
    {
        const size_t hbase = (size_t)h * S_LEN * HEAD_DIM + (size_t)s0 * HEAD_DIM;
        const __half* srcq = g_qh + hbase + tid * HEAD_DIM;
        const __half* srcl = g_ql + hbase + tid * HEAD_DIM;
        const __half* srck = g_kh + hbase + tid * HEAD_DIM;
        const __half* srcv = g_vh + hbase + tid * HEAD_DIM;
        uint32_t drow = sb + (uint32_t)(tid * AK) * 2;
#pragma unroll
        for (int c = 0; c < 10; c++) {
            cp16(drow + OFF_QH + c * 16, srcq + c * 8);
            cp16(drow + OFF_QL + c * 16, srcl + c * 8);
            cp16(drow + OFF_KH + c * 16, srck + c * 8);
            cp16(drow + OFF_VH + c * 16, srcv + c * 8);
        }
        CP_COMMIT();
    }
    CP_WAIT0();
    __syncthreads();

    const uint32_t kh_base = sb + OFF_KH + (uint32_t)(lr * AK + b_k_off) * 2;
    const uint32_t vh_base = sb + OFF_VH + (uint32_t)(a_row_off * AK) * 2;

    for (int qt = 0; qt < 2; qt++) {
        const uint32_t qh_base = sb + OFF_QH
            + (uint32_t)((qt * 128 + mr + a_row_off) * AK + a_k_off) * 2;
        const uint32_t ql_base = sb + OFF_QL
            + (uint32_t)((qt * 128 + mr + a_row_off) * AK + a_k_off) * 2;

        float oacc[10][4];
#pragma unroll
        for (int vb = 0; vb < 10; vb++)
#pragma unroll
            for (int k = 0; k < 4; k++) oacc[vb][k] = 0.0f;
        float m0 = -1e30f, m1 = -1e30f, l0 = 0.0f, l1 = 0.0f;

        for (int kt = 0; kt < 4; kt++) {
            // ---- S = Q K^T on this 64-wide KV tile (2-pass) ----
            float sacc[8][4];
#pragma unroll
            for (int nb = 0; nb < 8; nb++)
#pragma unroll
                for (int k = 0; k < 4; k++) sacc[nb][k] = 0.0f;

#pragma unroll
            for (int kb = 0; kb < 5; kb++) {
                uint32_t ah[4], al[4];
                ldsm_x4(ah, qh_base + kb * 32);
                ldsm_x4(al, ql_base + kb * 32);
#pragma unroll
                for (int nb = 0; nb < 8; nb++) {
                    uint32_t bh[2];
                    uint32_t ko = (uint32_t)((kt * 64 + nb * 8) * AK + kb * 16) * 2;
                    ldsm_x2(bh, kh_base + ko);
                    mma_f16(sacc[nb], ah, bh);
                    mma_f16(sacc[nb], al, bh);
                }
            }

            // ---- online softmax ----
            float t0 = -1e30f, t1 = -1e30f;
#pragma unroll
            for (int nb = 0; nb < 8; nb++) {
                t0 = fmaxf(t0, fmaxf(sacc[nb][0], sacc[nb][1]));
                t1 = fmaxf(t1, fmaxf(sacc[nb][2], sacc[nb][3]));
            }
            t0 = fmaxf(t0, __shfl_xor_sync(0xFFFFFFFFu, t0, 1));
            t0 = fmaxf(t0, __shfl_xor_sync(0xFFFFFFFFu, t0, 2));
            t1 = fmaxf(t1, __shfl_xor_sync(0xFFFFFFFFu, t1, 1));
            t1 = fmaxf(t1, __shfl_xor_sync(0xFFFFFFFFu, t1, 2));

            float nm0 = fmaxf(m0, t0);
            float nm1 = fmaxf(m1, t1);
            float corr0 = __expf(m0 - nm0);
            float corr1 = __expf(m1 - nm1);
            m0 = nm0; m1 = nm1;
            l0 *= corr0; l1 *= corr1;
#pragma unroll
            for (int vb = 0; vb < 10; vb++) {
                oacc[vb][0] *= corr0; oacc[vb][1] *= corr0;
                oacc[vb][2] *= corr1; oacc[vb][3] *= corr1;
            }

            uint32_t ph0[8], ph1[8];
#pragma unroll
            for (int nb = 0; nb < 8; nb++) {
                float p0 = __expf(sacc[nb][0] - m0);
                float p1 = __expf(sacc[nb][1] - m0);
                float p2 = __expf(sacc[nb][2] - m1);
                float p3 = __expf(sacc[nb][3] - m1);
                l0 += p0 + p1;
                l1 += p2 + p3;
                __half2 a = __floats2half2_rn(p0, p1);
                __half2 b = __floats2half2_rn(p2, p3);
                ph0[nb] = *(uint32_t*)&a;
                ph1[nb] = *(uint32_t*)&b;
            }

            // ---- O += P V (1-pass, V via ldmatrix.trans) ----
#pragma unroll
            for (int kc = 0; kc < 4; kc++) {
                uint32_t aH[4] = { ph0[2 * kc], ph1[2 * kc], ph0[2 * kc + 1], ph1[2 * kc + 1] };
                uint32_t vrow = vh_base + (uint32_t)((kt * 64 + kc * 16) * AK) * 2;
#pragma unroll
                for (int vb = 0; vb < 10; vb++) {
                    uint32_t bvh[2];
                    ldsm_x2_trans(bvh, vrow + vb * 16);
                    mma_f16(oacc[vb], aH, bvh);
                }
            }
        }

        // ---- finalize ----
        l0 += __shfl_xor_sync(0xFFFFFFFFu, l0, 1);
        l0 += __shfl_xor_sync(0xFFFFFFFFu, l0, 2);
        l1 += __shfl_xor_sync(0xFFFFFFFFu, l1, 1);
        l1 += __shfl_xor_sync(0xFFFFFFFFu, l1, 2);
        float inv0 = 1.0f / l0;
        float inv1 = 1.0f / l1;

        int row0 = s0 + qt * 128 + mr + g;
        float* op0 = &out[(size_t)row0 * (N_HEADS * HEAD_DIM) + h * HEAD_DIM + qc * 2];
        float* op1 = &out[(size_t)(row0 + 8) * (N_HEADS * HEAD_DIM) + h * HEAD_DIM + qc * 2];
#pragma unroll
        for (int vb = 0; vb < 10; vb++) {
            float2 a, b;
            a.x = oacc[vb][0] * inv0; a.y = oacc[vb][1] * inv0;
            b.x = oacc[vb][2] * inv1; b.y = oacc[vb][3] * inv1;
            *(float2*)&op0[vb * 8] = a;
            *(float2*)&op1[vb * 8] = b;
        }
    }
}

// ---------------------------------------------------------------------------
// Launcher
// ---------------------------------------------------------------------------
extern "C" void kernel_launch(void* const* d_in, const int* in_sizes, int n_in,
                              void* d_out, int out_size)
{
    const float* x    = (const float*)d_in[0];
    const int*   cu   = (const int*)d_in[1];
    const float* Wqkv = (const float*)d_in[2];
    const float* bqkv = (const float*)d_in[3];
    float* out = (float*)d_out;

    const int nseg = in_sizes[1] - 1;

    // 0) split x -> fp16 hi/lo; round W -> fp16 (8 floats/thread, 16B stores)
    split_kernel<<<(NX8 + NW8 + 255) / 256, 256>>>(x, Wqkv);

    // 1) QKV projection; Q blocks 2-pass, K/V blocks 1-pass
    cudaFuncSetAttribute(qkv_gemm_mma,
                         cudaFuncAttributeMaxDynamicSharedMemorySize, 2 * STAGE_BYTES);
    dim3 g1(N_QKV / GBN, S_LEN / GBM);   // 30 x 16
    qkv_gemm_mma<<<g1, 256, 2 * STAGE_BYTES>>>(bqkv);

    // 2) block-diagonal flash attention
    cudaFuncSetAttribute(attn_mma,
                         cudaFuncAttributeMaxDynamicSharedMemorySize, ATTN_SMEM);
    dim3 g2(nseg, N_HEADS);
    attn_mma<<<g2, 256, ATTN_SMEM>>>(cu, out);
}

// round 8
// speedup vs baseline: 4.6555x; 1.0149x over previous
#include <cuda_runtime.h>
#include <cuda_fp16.h>
#include <math.h>
#include <cstdint>

// Problem constants (fixed by the dataset)
#define S_LEN 2048
#define D_MODEL 1280
#define N_QKV 3840
#define N_HEADS 16
#define HEAD_DIM 80
#define SEG_LEN 256

// Global scratch: GEMM inputs (split) and GEMM outputs in attention layout
__device__ __half g_xh[S_LEN * D_MODEL];
__device__ __half g_xl[S_LEN * D_MODEL];
__device__ __half g_wh[N_QKV * D_MODEL];
// [head][s][d] fp16
__device__ __half g_qh[N_HEADS * S_LEN * HEAD_DIM];
__device__ __half g_ql[N_HEADS * S_LEN * HEAD_DIM];
__device__ __half g_kh[N_HEADS * S_LEN * HEAD_DIM];
__device__ __half g_vh[N_HEADS * S_LEN * HEAD_DIM];

// ---------------------------------------------------------------------------
// Helpers
// ---------------------------------------------------------------------------
__device__ __forceinline__ uint32_t smem_u32(const void* p) {
    uint32_t a;
    asm("{ .reg .u64 t; cvta.to.shared.u64 t, %1; cvt.u32.u64 %0, t; }"
        : "=r"(a) : "l"(p));
    return a;
}
__device__ __forceinline__ void ldsm_x4(uint32_t* r, uint32_t addr) {
    asm volatile("ldmatrix.sync.aligned.m8n8.x4.shared.b16 {%0,%1,%2,%3}, [%4];"
                 : "=r"(r[0]), "=r"(r[1]), "=r"(r[2]), "=r"(r[3]) : "r"(addr));
}
__device__ __forceinline__ void ldsm_x2(uint32_t* r, uint32_t addr) {
    asm volatile("ldmatrix.sync.aligned.m8n8.x2.shared.b16 {%0,%1}, [%2];"
                 : "=r"(r[0]), "=r"(r[1]) : "r"(addr));
}
__device__ __forceinline__ void ldsm_x2_trans(uint32_t* r, uint32_t addr) {
    asm volatile("ldmatrix.sync.aligned.m8n8.x2.trans.shared.b16 {%0,%1}, [%2];"
                 : "=r"(r[0]), "=r"(r[1]) : "r"(addr));
}
__device__ __forceinline__ void mma_f16(float* c, const uint32_t* a, const uint32_t* b) {
    asm volatile(
        "mma.sync.aligned.m16n8k16.row.col.f32.f16.f16.f32 "
        "{%0,%1,%2,%3}, {%4,%5,%6,%7}, {%8,%9}, {%0,%1,%2,%3};"
        : "+f"(c[0]), "+f"(c[1]), "+f"(c[2]), "+f"(c[3])
        : "r"(a[0]), "r"(a[1]), "r"(a[2]), "r"(a[3]), "r"(b[0]), "r"(b[1]));
}
__device__ __forceinline__ void cp16(uint32_t dst, const void* src) {
    asm volatile("cp.async.ca.shared.global [%0], [%1], 16;" :: "r"(dst), "l"(src));
}
#define CP_COMMIT() asm volatile("cp.async.commit_group;" ::: "memory")
#define CP_WAIT1() asm volatile("cp.async.wait_group 1;" ::: "memory")
#define CP_WAIT0() asm volatile("cp.async.wait_group 0;" ::: "memory")

__device__ __forceinline__ void split2h(float v, __half& h, __half& l) {
    h = __float2half(v);
    l = __float2half(v - __half2float(h));
}

// ---------------------------------------------------------------------------
// Kernel 0: split x -> fp16 hi/lo; round W -> fp16 hi. 8 floats per thread.
// ---------------------------------------------------------------------------
#define NX8 (S_LEN * D_MODEL / 8)   // 327680
#define NW8 (N_QKV * D_MODEL / 8)   // 614400

__global__ __launch_bounds__(256) void split_kernel(
    const float* __restrict__ x, const float* __restrict__ w)
{
    int i = blockIdx.x * blockDim.x + threadIdx.x;
    if (i >= NX8 + NW8) return;
    if (i < NX8) {
        float4 v0 = ((const float4*)x)[2 * i];
        float4 v1 = ((const float4*)x)[2 * i + 1];
        __half h0, h1, h2, h3, h4, h5, h6, h7;
        __half l0, l1, l2, l3, l4, l5, l6, l7;
        split2h(v0.x, h0, l0); split2h(v0.y, h1, l1);
        split2h(v0.z, h2, l2); split2h(v0.w, h3, l3);
        split2h(v1.x, h4, l4); split2h(v1.y, h5, l5);
        split2h(v1.z, h6, l6); split2h(v1.w, h7, l7);
        __half2 p0 = __halves2half2(h0, h1), p1 = __halves2half2(h2, h3);
        __half2 p2 = __halves2half2(h4, h5), p3 = __halves2half2(h6, h7);
        uint4 H;
        H.x = *(uint32_t*)&p0; H.y = *(uint32_t*)&p1;
        H.z = *(uint32_t*)&p2; H.w = *(uint32_t*)&p3;
        ((uint4*)g_xh)[i] = H;
        p0 = __halves2half2(l0, l1); p1 = __halves2half2(l2, l3);
        p2 = __halves2half2(l4, l5); p3 = __halves2half2(l6, l7);
        uint4 L;
        L.x = *(uint32_t*)&p0; L.y = *(uint32_t*)&p1;
        L.z = *(uint32_t*)&p2; L.w = *(uint32_t*)&p3;
        ((uint4*)g_xl)[i] = L;
    } else {
        int off = i - NX8;
        float4 v0 = ((const float4*)w)[2 * off];
        float4 v1 = ((const float4*)w)[2 * off + 1];
        __half2 p0 = __floats2half2_rn(v0.x, v0.y);
        __half2 p1 = __floats2half2_rn(v0.z, v0.w);
        __half2 p2 = __floats2half2_rn(v1.x, v1.y);
        __half2 p3 = __floats2half2_rn(v1.z, v1.w);
        uint4 H;
        H.x = *(uint32_t*)&p0; H.y = *(uint32_t*)&p1;
        H.z = *(uint32_t*)&p2; H.w = *(uint32_t*)&p3;
        ((uint4*)g_wh)[off] = H;
    }
}

// ---------------------------------------------------------------------------
// Kernel 1: QKV GEMM. Q columns (bn<1280): fp16 2-pass (split-A).
// K/V columns: fp16 1-pass. cp.async double-buffered.
// Epilogue writes fp16 [h][s][d] directly.
// ---------------------------------------------------------------------------
#define GBM 128
#define GBN 128
#define GBK 32
#define NCHUNK (D_MODEL / GBK)   // 40
#define AST 40                   // smem row stride (halfs) = 80 B, conflict-free
#define ARR_BYTES (128 * AST * 2)        // 10240
#define STAGE_BYTES (3 * ARR_BYTES)      // 30720

__global__ __launch_bounds__(256, 2) void qkv_gemm_mma(
    const float* __restrict__ bias)
{
    extern __shared__ char smem[];
    const uint32_t sb = smem_u32(smem);

    const int tid = threadIdx.x;
    const int wid = tid >> 5;
    const int lane = tid & 31;
    const int wm = wid >> 2;
    const int wn = wid & 3;
    const int bn = blockIdx.x * GBN;
    const int bm = blockIdx.y * GBM;
    const bool needQ = (bn < D_MODEL);

    float acc[4][4][4];
#pragma unroll
    for (int i = 0; i < 4; i++)
#pragma unroll
        for (int j = 0; j < 4; j++)
#pragma unroll
            for (int k = 0; k < 4; k++) acc[i][j][k] = 0.0f;

    const int lr = lane & 7;
    const int lsub = lane >> 3;
    const int a_row_off = (lsub & 1) * 8 + lr;
    const int a_k_off = (lsub >> 1) * 8;
    const int b_k_off = (lsub & 1) * 8;

    auto load_stage = [&](int c, int st) {
        uint32_t dbase = sb + st * STAGE_BYTES;
        size_t k0 = (size_t)c * GBK;
#pragma unroll
        for (int i = 0; i < 2; i++) {
            int id = i * 256 + tid;
            int row = id >> 2, ch = id & 3;
            uint32_t d = dbase + (uint32_t)(row * AST + ch * 8) * 2;
            size_t so = k0 + ch * 8;
            cp16(d + 0 * ARR_BYTES, g_xh + (size_t)(bm + row) * D_MODEL + so);
            if (needQ)
                cp16(d + 1 * ARR_BYTES, g_xl + (size_t)(bm + row) * D_MODEL + so);
            cp16(d + 2 * ARR_BYTES, g_wh + (size_t)(bn + row) * D_MODEL + so);
        }
        CP_COMMIT();
    };

    load_stage(0, 0);

    for (int c = 0; c < NCHUNK; c++) {
        const int cur = c & 1;
        if (c + 1 < NCHUNK) {
            load_stage(c + 1, cur ^ 1);
            CP_WAIT1();
        } else {
            CP_WAIT0();
        }
        __syncthreads();

        const uint32_t sAh = sb + cur * STAGE_BYTES;
        const uint32_t sAl = sAh + ARR_BYTES;
        const uint32_t sBh = sAh + 2 * ARR_BYTES;

        if (needQ) {
#pragma unroll
            for (int ks = 0; ks < 2; ks++) {
                uint32_t ah[4][4], al[4][4];
#pragma unroll
                for (int mb = 0; mb < 4; mb++) {
                    uint32_t off = (uint32_t)((wm * 64 + mb * 16 + a_row_off) * AST
                                              + ks * 16 + a_k_off) * 2;
                    ldsm_x4(ah[mb], sAh + off);
                    ldsm_x4(al[mb], sAl + off);
                }
#pragma unroll
                for (int nb = 0; nb < 4; nb++) {
                    uint32_t bh[2];
                    uint32_t off = (uint32_t)((wn * 32 + nb * 8 + lr) * AST
                                              + ks * 16 + b_k_off) * 2;
                    ldsm_x2(bh, sBh + off);
#pragma unroll
                    for (int mb = 0; mb < 4; mb++) {
                        mma_f16(acc[mb][nb], ah[mb], bh);
                        mma_f16(acc[mb][nb], al[mb], bh);
                    }
                }
            }
        } else {
#pragma unroll
            for (int ks = 0; ks < 2; ks++) {
                uint32_t ah[4][4];
#pragma unroll
                for (int mb = 0; mb < 4; mb++) {
                    uint32_t off = (uint32_t)((wm * 64 + mb * 16 + a_row_off) * AST
                                              + ks * 16 + a_k_off) * 2;
                    ldsm_x4(ah[mb], sAh + off);
                }
#pragma unroll
                for (int nb = 0; nb < 4; nb++) {
                    uint32_t bh[2];
                    uint32_t off = (uint32_t)((wn * 32 + nb * 8 + lr) * AST
                                              + ks * 16 + b_k_off) * 2;
                    ldsm_x2(bh, sBh + off);
#pragma unroll
                    for (int mb = 0; mb < 4; mb++)
                        mma_f16(acc[mb][nb], ah[mb], bh);
                }
            }
        }
        __syncthreads();
    }

    // epilogue: bias add, route to Q(scaled, split)/K/V fp16 [h][s][d]
    const float scale = 0.111803398874989485f;  // 1/sqrt(80)
    const int g = lane >> 2;
    const int cc = lane & 3;
#pragma unroll
    for (int nb = 0; nb < 4; nb++) {
        int col = bn + wn * 32 + nb * 8 + cc * 2;
        int sec = col / D_MODEL;          // 0=q 1=k 2=v
        int f = col - sec * D_MODEL;
        int h = f / HEAD_DIM;
        int d = f - h * HEAD_DIM;
        float2 bv = *(const float2*)&bias[col];
        size_t hb = (size_t)h * S_LEN * HEAD_DIM + d;
#pragma unroll
        for (int mb = 0; mb < 4; mb++) {
#pragma unroll
            for (int rr = 0; rr < 2; rr++) {
                int row = bm + wm * 64 + mb * 16 + g + rr * 8;
                float v0 = acc[mb][nb][rr * 2 + 0] + bv.x;
                float v1 = acc[mb][nb][rr * 2 + 1] + bv.y;
                size_t idx = hb + (size_t)row * HEAD_DIM;
                if (sec == 0) {
                    v0 *= scale; v1 *= scale;
                    __half h0, l0h, h1, l1h;
                    split2h(v0, h0, l0h);
                    split2h(v1, h1, l1h);
                    *(__half2*)&g_qh[idx] = __halves2half2(h0, h1);
                    *(__half2*)&g_ql[idx] = __halves2half2(l0h, l1h);
                } else if (sec == 1) {
                    *(__half2*)&g_kh[idx] = __floats2half2_rn(v0, v1);
                } else {
                    *(__half2*)&g_vh[idx] = __floats2half2_rn(v0, v1);
                }
            }
        }
    }
}

// ---------------------------------------------------------------------------
// Kernel 2: block-diagonal flash attention, fp16, 512 threads / 16 warps.
// Warps 0-7 own Q rows [0,128), warps 8-15 own [128,256) -> 2x warps/SMSP
// to hide the QK->softmax->PV dependency chain.
// QK^T: 2-pass (Q split); PV: 1-pass. V via ldmatrix.trans.
// ---------------------------------------------------------------------------
#define AK 88    // row stride (halfs): 176 B, conflict-free

#define OFF_QH 0
#define OFF_QL (OFF_QH + 256 * AK * 2)    // 45056
#define OFF_KH (OFF_QL + 256 * AK * 2)    // 90112
#define OFF_VH (OFF_KH + 256 * AK * 2)    // 135168
#define ATTN_SMEM (OFF_VH + 256 * AK * 2) // 180224

__global__ __launch_bounds__(512, 1) void attn_mma(
    const int* __restrict__ cu_seqlens,
    float* __restrict__ out)
{
    extern __shared__ char smem[];
    const uint32_t sb = smem_u32(smem);

    const int seg = blockIdx.x;
    const int h = blockIdx.y;
    const int s0 = cu_seqlens[seg];

    const int tid = threadIdx.x;
    const int wid = tid >> 5;
    const int lane = tid & 31;
    const int qt = wid >> 3;        // 0 or 1: which 128-row Q tile
    const int w8 = wid & 7;         // warp within tile
    const int lr = lane & 7;
    const int lsub = lane >> 3;
    const int a_row_off = (lsub & 1) * 8 + lr;
    const int a_k_off = (lsub >> 1) * 8;
    const int b_k_off = (lsub & 1) * 8;
    const int g = lane >> 2;
    const int qc = lane & 3;
    const int mr = w8 * 16;

    // ---- cp.async all tiles: thread = (row, half-row); 5 chunks per array ----
    {
        const int row = tid >> 1;
        const int half = tid & 1;
        const size_t hbase = (size_t)h * S_LEN * HEAD_DIM + (size_t)s0 * HEAD_DIM
                             + (size_t)row * HEAD_DIM + half * 40;
        const __half* srcq = g_qh + hbase;
        const __half* srcl = g_ql + hbase;
        const __half* srck = g_kh + hbase;
        const __half* srcv = g_vh + hbase;
        uint32_t drow = sb + (uint32_t)(row * AK + half * 40) * 2;
#pragma unroll
        for (int c = 0; c < 5; c++) {
            cp16(drow + OFF_QH + c * 16, srcq + c * 8);
            cp16(drow + OFF_QL + c * 16, srcl + c * 8);
            cp16(drow + OFF_KH + c * 16, srck + c * 8);
            cp16(drow + OFF_VH + c * 16, srcv + c * 8);
        }
        CP_COMMIT();
    }
    CP_WAIT0();
    __syncthreads();

    const uint32_t kh_base = sb + OFF_KH + (uint32_t)(lr * AK + b_k_off) * 2;
    const uint32_t vh_base = sb + OFF_VH + (uint32_t)(a_row_off * AK) * 2;
    const uint32_t qh_base = sb + OFF_QH
        + (uint32_t)((qt * 128 + mr + a_row_off) * AK + a_k_off) * 2;
    const uint32_t ql_base = sb + OFF_QL
        + (uint32_t)((qt * 128 + mr + a_row_off) * AK + a_k_off) * 2;

    float oacc[10][4];
#pragma unroll
    for (int vb = 0; vb < 10; vb++)
#pragma unroll
        for (int k = 0; k < 4; k++) oacc[vb][k] = 0.0f;
    float m0 = -1e30f, m1 = -1e30f, l0 = 0.0f, l1 = 0.0f;

    for (int kt = 0; kt < 4; kt++) {
        // ---- S = Q K^T on this 64-wide KV tile (2-pass) ----
        float sacc[8][4];
#pragma unroll
        for (int nb = 0; nb < 8; nb++)
#pragma unroll
            for (int k = 0; k < 4; k++) sacc[nb][k] = 0.0f;

#pragma unroll
        for (int kb = 0; kb < 5; kb++) {
            uint32_t ah[4], al[4];
            ldsm_x4(ah, qh_base + kb * 32);
            ldsm_x4(al, ql_base + kb * 32);
#pragma unroll
            for (int nb = 0; nb < 8; nb++) {
                uint32_t bh[2];
                uint32_t ko = (uint32_t)((kt * 64 + nb * 8) * AK + kb * 16) * 2;
                ldsm_x2(bh, kh_base + ko);
                mma_f16(sacc[nb], ah, bh);
                mma_f16(sacc[nb], al, bh);
            }
        }

        // ---- online softmax ----
        float t0 = -1e30f, t1 = -1e30f;
#pragma unroll
        for (int nb = 0; nb < 8; nb++) {
            t0 = fmaxf(t0, fmaxf(sacc[nb][0], sacc[nb][1]));
            t1 = fmaxf(t1, fmaxf(sacc[nb][2], sacc[nb][3]));
        }
        t0 = fmaxf(t0, __shfl_xor_sync(0xFFFFFFFFu, t0, 1));
        t0 = fmaxf(t0, __shfl_xor_sync(0xFFFFFFFFu, t0, 2));
        t1 = fmaxf(t1, __shfl_xor_sync(0xFFFFFFFFu, t1, 1));
        t1 = fmaxf(t1, __shfl_xor_sync(0xFFFFFFFFu, t1, 2));

        float nm0 = fmaxf(m0, t0);
        float nm1 = fmaxf(m1, t1);
        float corr0 = __expf(m0 - nm0);
        float corr1 = __expf(m1 - nm1);
        m0 = nm0; m1 = nm1;
        l0 *= corr0; l1 *= corr1;
#pragma unroll
        for (int vb = 0; vb < 10; vb++) {
            oacc[vb][0] *= corr0; oacc[vb][1] *= corr0;
            oacc[vb][2] *= corr1; oacc[vb][3] *= corr1;
        }

        uint32_t ph0[8], ph1[8];
#pragma unroll
        for (int nb = 0; nb < 8; nb++) {
            float p0 = __expf(sacc[nb][0] - m0);
            float p1 = __expf(sacc[nb][1] - m0);
            float p2 = __expf(sacc[nb][2] - m1);
            float p3 = __expf(sacc[nb][3] - m1);
            l0 += p0 + p1;
            l1 += p2 + p3;
            __half2 a = __floats2half2_rn(p0, p1);
            __half2 b = __floats2half2_rn(p2, p3);
            ph0[nb] = *(uint32_t*)&a;
            ph1[nb] = *(uint32_t*)&b;
        }

        // ---- O += P V (1-pass, V via ldmatrix.trans) ----
#pragma unroll
        for (int kc = 0; kc < 4; kc++) {
            uint32_t aH[4] = { ph0[2 * kc], ph1[2 * kc], ph0[2 * kc + 1], ph1[2 * kc + 1] };
            uint32_t vrow = vh_base + (uint32_t)((kt * 64 + kc * 16) * AK) * 2;
#pragma unroll
            for (int vb = 0; vb < 10; vb++) {
                uint32_t bvh[2];
                ldsm_x2_trans(bvh, vrow + vb * 16);
                mma_f16(oacc[vb], aH, bvh);
            }
        }
    }

    // ---- finalize ----
    l0 += __shfl_xor_sync(0xFFFFFFFFu, l0, 1);
    l0 += __shfl_xor_sync(0xFFFFFFFFu, l0, 2);
    l1 += __shfl_xor_sync(0xFFFFFFFFu, l1, 1);
    l1 += __shfl_xor_sync(0xFFFFFFFFu, l1, 2);
    float inv0 = 1.0f / l0;
    float inv1 = 1.0f / l1;

    int row0 = s0 + qt * 128 + mr + g;
    float* op0 = &out[(size_t)row0 * (N_HEADS * HEAD_DIM) + h * HEAD_DIM + qc * 2];
    float* op1 = &out[(size_t)(row0 + 8) * (N_HEADS * HEAD_DIM) + h * HEAD_DIM + qc * 2];
#pragma unroll
    for (int vb = 0; vb < 10; vb++) {
        float2 a, b;
        a.x = oacc[vb][0] * inv0; a.y = oacc[vb][1] * inv0;
        b.x = oacc[vb][2] * inv1; b.y = oacc[vb][3] * inv1;
        *(float2*)&op0[vb * 8] = a;
        *(float2*)&op1[vb * 8] = b;
    }
}

// ---------------------------------------------------------------------------
// Launcher
// ---------------------------------------------------------------------------
extern "C" void kernel_launch(void* const* d_in, const int* in_sizes, int n_in,
                              void* d_out, int out_size)
{
    const float* x    = (const float*)d_in[0];
    const int*   cu   = (const int*)d_in[1];
    const float* Wqkv = (const float*)d_in[2];
    const float* bqkv = (const float*)d_in[3];
    float* out = (float*)d_out;

    const int nseg = in_sizes[1] - 1;

    // 0) split x -> fp16 hi/lo; round W -> fp16
    split_kernel<<<(NX8 + NW8 + 255) / 256, 256>>>(x, Wqkv);

    // 1) QKV projection; Q blocks 2-pass, K/V blocks 1-pass
    cudaFuncSetAttribute(qkv_gemm_mma,
                         cudaFuncAttributeMaxDynamicSharedMemorySize, 2 * STAGE_BYTES);
    dim3 g1(N_QKV / GBN, S_LEN / GBM);   // 30 x 16
    qkv_gemm_mma<<<g1, 256, 2 * STAGE_BYTES>>>(bqkv);

    // 2) block-diagonal flash attention (512 threads, 16 warps)
    cudaFuncSetAttribute(attn_mma,
                         cudaFuncAttributeMaxDynamicSharedMemorySize, ATTN_SMEM);
    dim3 g2(nseg, N_HEADS);
    attn_mma<<<g2, 512, ATTN_SMEM>>>(cu, out);
}